// round 7
// baseline (speedup 1.0000x reference)
#include <cuda_runtime.h>
#include <cuda_bf16.h>
#include <math.h>
#include <stdint.h>

#define NB 64
#define TT 512
#define NI 256
#define NH 1024
#define NOISEF 0.1f
#define NBLK 64           // scan blocks: each owns 16 j-columns, full K
#define JPB 16

// ---- static device scratch ----
__device__ float g_h32[2][NB * NH];          // fp32 hidden state [b][j]
__device__ unsigned int g_hpk[2][NB * NH];   // packed bf16 hi<<16|lo of h [b][k]
__device__ float g_alpha[NH];
__device__ float g_wt[NI * NH];              // transposed in_w for proj (f32)
__device__ __nv_bfloat16 g_wthi[NH * NH];    // [j][k] = bf16_hi(W[k][j])
__device__ __nv_bfloat16 g_wtlo[NH * NH];    // [j][k] = residual
__device__ int g_done;

// smem layout for scan
#define SMA_HI 0
#define SMA_LO 33024
#define SMB    66048
#define BUFSZ  34816
#define BHOFF  0
#define BLOFF  17408
#define AROWB  2064          // 1024 bf16 + 16B pad
#define BROWB  272           // 128 bf16 + 16B pad
#define SM_TOT (66048 + 2 * 34816)   // 135680

static __device__ __forceinline__ uint32_t smem_u32(const void* p) {
    uint32_t a;
    asm("{ .reg .u64 t; cvta.to.shared.u64 t, %1; cvt.u32.u64 %0, t; }" : "=r"(a) : "l"(p));
    return a;
}

#define LDSM4(r, a)                                                             \
    asm volatile("ldmatrix.sync.aligned.m8n8.x4.shared.b16 {%0,%1,%2,%3}, [%4];" \
        : "=r"((r)[0]), "=r"((r)[1]), "=r"((r)[2]), "=r"((r)[3]) : "r"(a))

#define MMA16816(d, a, b0, b1)                                                  \
    asm volatile("mma.sync.aligned.m16n8k16.row.col.f32.bf16.bf16.f32 "         \
        "{%0,%1,%2,%3}, {%4,%5,%6,%7}, {%8,%9}, {%0,%1,%2,%3};"                 \
        : "+f"((d)[0]), "+f"((d)[1]), "+f"((d)[2]), "+f"((d)[3])                \
        : "r"((a)[0]), "r"((a)[1]), "r"((a)[2]), "r"((a)[3]), "r"(b0), "r"(b1))

static __device__ __forceinline__ uint32_t packhl(float v) {
    __nv_bfloat16 h = __float2bfloat16(v);
    __nv_bfloat16 lo = __float2bfloat16(v - __bfloat162float(h));
    return ((uint32_t)__bfloat16_as_ushort(h) << 16) | __bfloat16_as_ushort(lo);
}

// ---- f32x2 helpers for proj ----
__device__ __forceinline__ unsigned long long pk2(float a, float b) {
    unsigned long long r;
    asm("mov.b64 %0, {%1, %2};" : "=l"(r) : "r"(__float_as_uint(a)), "r"(__float_as_uint(b)));
    return r;
}
__device__ __forceinline__ float2 upk2(unsigned long long v) {
    unsigned int lo, hi;
    asm("mov.b64 {%0, %1}, %2;" : "=r"(lo), "=r"(hi) : "l"(v));
    return make_float2(__uint_as_float(lo), __uint_as_float(hi));
}
__device__ __forceinline__ unsigned long long ffma2(unsigned long long a,
                                                    unsigned long long b,
                                                    unsigned long long c) {
    unsigned long long d;
    asm("fma.rn.f32x2 %0, %1, %2, %3;" : "=l"(d) : "l"(a), "l"(b), "l"(c));
    return d;
}

__global__ void init_kernel(const float* __restrict__ taus) {
    int idx = blockIdx.x * blockDim.x + threadIdx.x;
    if (idx < NB * NH) { g_h32[0][idx] = 0.0f; g_hpk[0][idx] = 0u; }
    if (idx < NH) {
        float s = 1.0f / (1.0f + expf(-taus[idx]));
        g_alpha[idx] = 10.0f / (s * 90.0f + 10.0f);
    }
    if (idx == 0) g_done = 0;
}

// transpose in_w [H][I] -> g_wt [I][H] (f32, for proj)
__global__ void transpose_kernel(const float* __restrict__ w) {
    __shared__ float t[32][33];
    int bi = blockIdx.x * 32;
    int bh = blockIdx.y * 32;
    int tx = threadIdx.x, ty = threadIdx.y;
    for (int i = ty; i < 32; i += 8) t[i][tx] = w[(bh + i) * NI + bi + tx];
    __syncthreads();
    for (int i = ty; i < 32; i += 8) g_wt[(bi + i) * NH + bh + tx] = t[tx][i];
}

// W [k][j] -> g_wthi/g_wtlo [j][k] bf16 split
__global__ void wsplit_kernel(const float* __restrict__ W) {
    __shared__ float t[32][33];
    int bk = blockIdx.x * 32;
    int bj = blockIdx.y * 32;
    int tx = threadIdx.x, ty = threadIdx.y;
    for (int i = ty; i < 32; i += 8) t[i][tx] = W[(bk + i) * NH + bj + tx];
    __syncthreads();
    for (int i = ty; i < 32; i += 8) {
        float v = t[tx][i];                       // W[bk+tx][bj+i]
        __nv_bfloat16 hi = __float2bfloat16(v);
        float r = v - __bfloat162float(hi);
        g_wthi[(bj + i) * NH + bk + tx] = hi;
        g_wtlo[(bj + i) * NH + bk + tx] = __float2bfloat16(r);
    }
}

// ---------------------------------------------------------------------------
// Input projection (FFMA2, unchanged)
// ---------------------------------------------------------------------------
__global__ void __launch_bounds__(256) proj_kernel(
    const float* __restrict__ x, const float* __restrict__ bias,
    const float* __restrict__ eps, float* __restrict__ out)
{
    __shared__ float xs[64][20];
    __shared__ float ws[16][68];
    const int tid = threadIdx.x;
    const int rg = tid >> 4, cg = tid & 15;
    const int r4 = rg << 2, c4 = cg << 2;
    const int j0 = blockIdx.x * 64;
    const int r0 = blockIdx.y * 64;
    const int lr = tid >> 2, lk = (tid & 3) << 2;
    const int wk = tid >> 4, wj = (tid & 15) << 2;

    unsigned long long acc[4][2];
#pragma unroll
    for (int i = 0; i < 4; i++) { acc[i][0] = 0ull; acc[i][1] = 0ull; }

    for (int k0 = 0; k0 < NI; k0 += 16) {
        *(float4*)&xs[lr][lk] = *(const float4*)(x + (r0 + lr) * NI + k0 + lk);
        *(float4*)&ws[wk][wj] = *(const float4*)(g_wt + (k0 + wk) * NH + j0 + wj);
        __syncthreads();
#pragma unroll
        for (int k = 0; k < 16; k += 4) {
            ulonglong2 b0 = *(const ulonglong2*)&ws[k + 0][c4];
            ulonglong2 b1 = *(const ulonglong2*)&ws[k + 1][c4];
            ulonglong2 b2 = *(const ulonglong2*)&ws[k + 2][c4];
            ulonglong2 b3 = *(const ulonglong2*)&ws[k + 3][c4];
#pragma unroll
            for (int i = 0; i < 4; i++) {
                float4 a = *(const float4*)&xs[r4 + i][k];
                unsigned long long p;
                p = pk2(a.x, a.x); acc[i][0] = ffma2(p, b0.x, acc[i][0]); acc[i][1] = ffma2(p, b0.y, acc[i][1]);
                p = pk2(a.y, a.y); acc[i][0] = ffma2(p, b1.x, acc[i][0]); acc[i][1] = ffma2(p, b1.y, acc[i][1]);
                p = pk2(a.z, a.z); acc[i][0] = ffma2(p, b2.x, acc[i][0]); acc[i][1] = ffma2(p, b2.y, acc[i][1]);
                p = pk2(a.w, a.w); acc[i][0] = ffma2(p, b3.x, acc[i][0]); acc[i][1] = ffma2(p, b3.y, acc[i][1]);
            }
        }
        __syncthreads();
    }

    float4 bi = *(const float4*)(bias + j0 + c4);
#pragma unroll
    for (int i = 0; i < 4; i++) {
        int r = r0 + r4 + i;
        int off = r * NH + j0 + c4;
        float4 ev = *(const float4*)(eps + off);
        float2 lo = upk2(acc[i][0]);
        float2 hi = upk2(acc[i][1]);
        float4 o;
        o.x = lo.x + bi.x + NOISEF * ev.x;
        o.y = lo.y + bi.y + NOISEF * ev.y;
        o.z = hi.x + bi.z + NOISEF * ev.z;
        o.w = hi.y + bi.w + NOISEF * ev.w;
        *(float4*)(out + off) = o;
    }
}

// ---------------------------------------------------------------------------
// Persistent scan: 64 blocks, each owns 16 j-columns with full K=1024.
// No split-K exchange; ONE rendezvous per step. Streams packed h in 8
// double-buffered chunks overlapped with HMMA.
// Warp w handles batch rows [8w, 8w+8): full-K accumulation in registers.
// ---------------------------------------------------------------------------
__global__ void __launch_bounds__(256) scan_kernel(float* __restrict__ out)
{
    extern __shared__ char smem[];
    const uint32_t sbase = smem_u32(smem);
    const int tid = threadIdx.x;
    const int l = tid & 31, w = tid >> 5;
    const int j0 = blockIdx.x * JPB;
    const int wn = w * 8;

    // Load resident A tiles: W^T hi/lo rows [j0..j0+16) x full K
    for (int idx = tid; idx < 2048; idx += 256) {
        int r = idx >> 7, cb = (idx & 127) * 16;
        *(uint4*)(smem + SMA_HI + r * AROWB + cb) =
            *(const uint4*)((const char*)(g_wthi + (size_t)(j0 + r) * NH) + cb);
        *(uint4*)(smem + SMA_LO + r * AROWB + cb) =
            *(const uint4*)((const char*)(g_wtlo + (size_t)(j0 + r) * NH) + cb);
    }

    // ldmatrix lane addresses
    const uint32_t aHi = sbase + SMA_HI + (l & 15) * AROWB + (l >> 4) * 16;
    const uint32_t aLo = aHi + (SMA_LO - SMA_HI);
    const uint32_t bOff = (uint32_t)((wn + (l & 7)) * BROWB + (l >> 3) * 16);

    // epilogue coords: 4 outputs per lane: (j0+l/4, eb), (.., eb+1), (+8 rows)
    const int ejA = j0 + (l >> 2);
    const int ejB = ejA + 8;
    const int eb = wn + 2 * (l & 3);
    const float alA = g_alpha[ejA], alB = g_alpha[ejB];

    __syncthreads();

    for (int t = 0; t < TT; t++) {
        if (t > 0) {
            if (tid == 0) { while (__ldcg(&g_done) < NBLK * t) __nanosleep(16); }
            __syncthreads();
        }
        const unsigned int* hsrc = g_hpk[t & 1];

        uint4 r[8];
        // stage chunk 0 into buf 0
#pragma unroll
        for (int i = 0; i < 8; i++) {
            int idx = tid + 256 * i;
            r[i] = __ldcg((const uint4*)(hsrc + (idx >> 5) * NH + (idx & 31) * 4));
        }
#pragma unroll
        for (int i = 0; i < 8; i++) {
            int idx = tid + 256 * i;
            char* dh = smem + SMB + (idx >> 5) * BROWB + (idx & 31) * 8;
            uint32_t h0 = __byte_perm(r[i].x, r[i].y, 0x7632);
            uint32_t l0 = __byte_perm(r[i].x, r[i].y, 0x5410);
            uint32_t h1 = __byte_perm(r[i].z, r[i].w, 0x7632);
            uint32_t l1 = __byte_perm(r[i].z, r[i].w, 0x5410);
            *(uint2*)(dh + BHOFF) = make_uint2(h0, h1);
            *(uint2*)(dh + BLOFF) = make_uint2(l0, l1);
        }

        float acc[4] = {0.0f, 0.0f, 0.0f, 0.0f};
#pragma unroll
        for (int c = 0; c < 8; c++) {
            __syncthreads();   // buf[c&1] staged & prior readers done
            if (c < 7) {
#pragma unroll
                for (int i = 0; i < 8; i++) {
                    int idx = tid + 256 * i;
                    r[i] = __ldcg((const uint4*)(hsrc + (idx >> 5) * NH + 128 * (c + 1) + (idx & 31) * 4));
                }
            }
            const uint32_t bb = sbase + SMB + (c & 1) * BUFSZ + bOff;
#pragma unroll
            for (int kp = 0; kp < 4; kp++) {
                uint32_t bh[4], bl4[4];
                LDSM4(bh, bb + BHOFF + kp * 64);
                LDSM4(bl4, bb + BLOFF + kp * 64);
#pragma unroll
                for (int s = 0; s < 2; s++) {
                    uint32_t ah[4], alr[4];
                    const uint32_t sg = (c * 8 + kp * 2 + s) * 32;
                    LDSM4(ah, aHi + sg);
                    LDSM4(alr, aLo + sg);
                    MMA16816(acc, ah, bh[2 * s], bh[2 * s + 1]);
                    MMA16816(acc, ah, bl4[2 * s], bl4[2 * s + 1]);
                    MMA16816(acc, alr, bh[2 * s], bh[2 * s + 1]);
                }
            }
            if (c < 7) {
#pragma unroll
                for (int i = 0; i < 8; i++) {
                    int idx = tid + 256 * i;
                    char* dh = smem + SMB + ((c + 1) & 1) * BUFSZ + (idx >> 5) * BROWB + (idx & 31) * 8;
                    uint32_t h0 = __byte_perm(r[i].x, r[i].y, 0x7632);
                    uint32_t l0 = __byte_perm(r[i].x, r[i].y, 0x5410);
                    uint32_t h1 = __byte_perm(r[i].z, r[i].w, 0x7632);
                    uint32_t l1 = __byte_perm(r[i].z, r[i].w, 0x5410);
                    *(uint2*)(dh + BHOFF) = make_uint2(h0, h1);
                    *(uint2*)(dh + BLOFF) = make_uint2(l0, l1);
                }
            }
        }

        // local epilogue: acc holds final hW for (j, b) patch
        {
            const float* hin = g_h32[t & 1];
            float* h32o = g_h32[(t + 1) & 1];
            unsigned int* hpko = g_hpk[(t + 1) & 1];
            const long o0 = ((long)eb * TT + t) * NH;
            const long o1 = ((long)(eb + 1) * TT + t) * NH;
            float p00 = out[o0 + ejA], p01 = out[o1 + ejA];
            float p10 = out[o0 + ejB], p11 = out[o1 + ejB];
            float h00 = hin[eb * NH + ejA], h01 = hin[(eb + 1) * NH + ejA];
            float h10 = hin[eb * NH + ejB], h11 = hin[(eb + 1) * NH + ejB];
            float n00 = (1.0f - alA) * h00 + alA * tanhf(p00 + acc[0]);
            float n01 = (1.0f - alA) * h01 + alA * tanhf(p01 + acc[1]);
            float n10 = (1.0f - alB) * h10 + alB * tanhf(p10 + acc[2]);
            float n11 = (1.0f - alB) * h11 + alB * tanhf(p11 + acc[3]);
            out[o0 + ejA] = n00; out[o1 + ejA] = n01;
            out[o0 + ejB] = n10; out[o1 + ejB] = n11;
            h32o[eb * NH + ejA] = n00; h32o[(eb + 1) * NH + ejA] = n01;
            h32o[eb * NH + ejB] = n10; h32o[(eb + 1) * NH + ejB] = n11;
            hpko[eb * NH + ejA] = packhl(n00); hpko[(eb + 1) * NH + ejA] = packhl(n01);
            hpko[eb * NH + ejB] = packhl(n10); hpko[(eb + 1) * NH + ejB] = packhl(n11);
        }

        __threadfence();
        __syncthreads();
        if (tid == 0) atomicAdd(&g_done, 1);
    }
}

extern "C" void kernel_launch(void* const* d_in, const int* in_sizes, int n_in,
                              void* d_out, int out_size) {
    const float* x    = (const float*)d_in[0];  // [B,T,I]
    const float* eps  = (const float*)d_in[1];  // [B,T,H]
    const float* in_w = (const float*)d_in[2];  // [H,I]
    const float* in_b = (const float*)d_in[3];  // [H]
    const float* W    = (const float*)d_in[4];  // [H,H]
    const float* taus = (const float*)d_in[5];  // [H]
    float* out = (float*)d_out;                 // [B,T,H]

    static int attr_done = 0;
    if (!attr_done) {
        cudaFuncSetAttribute(scan_kernel, cudaFuncAttributeMaxDynamicSharedMemorySize, SM_TOT);
        attr_done = 1;
    }

    init_kernel<<<(NB * NH + 255) / 256, 256>>>(taus);
    transpose_kernel<<<dim3(NI / 32, NH / 32), dim3(32, 8)>>>(in_w);
    wsplit_kernel<<<dim3(NH / 32, NH / 32), dim3(32, 8)>>>(W);

    dim3 pgrid(NH / 64, (NB * TT) / 64);
    proj_kernel<<<pgrid, 256>>>(x, in_b, eps, out);

    scan_kernel<<<NBLK, 256, SM_TOT>>>(out);
}

// round 8
// speedup vs baseline: 1.9535x; 1.9535x over previous
#include <cuda_runtime.h>
#include <cuda_bf16.h>
#include <math.h>
#include <stdint.h>

#define NB 64
#define TT 512
#define NI 256
#define NH 1024
#define NOISEF 0.1f
#define NKS 8             // k-slices of 128
#define NTILE 16          // j-tiles of 64
#define NBLK 128

// ---- static device scratch ----
__device__ float g_h32[2][NB * NH];          // fp32 hidden state [b][j], double buf
__device__ unsigned int g_hpk[2][NB * NH];   // packed bf16 hi<<16|lo of h
__device__ float g_part[NKS][NB * NH];       // split-K slabs, layout [b][j]
__device__ float g_alpha[NH];
__device__ float g_wt[NI * NH];              // transposed in_w for proj (f32)
__device__ __nv_bfloat16 g_wthi[NH * NH];    // [j][k] = bf16_hi(W[k][j])
__device__ __nv_bfloat16 g_wtlo[NH * NH];    // [j][k] = residual
__device__ int g_cnt[NTILE];                 // slab arrivals per tile (monotonic)
__device__ int g_ecnt[NTILE];                // epilogue parts per tile (monotonic)

// smem layout (272B-padded rows of 128 bf16 for conflict-free ldmatrix)
#define SM_WHI 0
#define SM_WLO 17408
#define SM_BHI 34816
#define SM_BLO 52224
#define SM_TOTAL 69632
#define ROWB 272

static __device__ __forceinline__ uint32_t smem_u32(const void* p) {
    uint32_t a;
    asm("{ .reg .u64 t; cvta.to.shared.u64 t, %1; cvt.u32.u64 %0, t; }" : "=r"(a) : "l"(p));
    return a;
}

#define LDSM4(r, a)                                                             \
    asm volatile("ldmatrix.sync.aligned.m8n8.x4.shared.b16 {%0,%1,%2,%3}, [%4];" \
        : "=r"((r)[0]), "=r"((r)[1]), "=r"((r)[2]), "=r"((r)[3]) : "r"(a))

#define MMA16816(d, a, b0, b1)                                                  \
    asm volatile("mma.sync.aligned.m16n8k16.row.col.f32.bf16.bf16.f32 "         \
        "{%0,%1,%2,%3}, {%4,%5,%6,%7}, {%8,%9}, {%0,%1,%2,%3};"                 \
        : "+f"((d)[0]), "+f"((d)[1]), "+f"((d)[2]), "+f"((d)[3])                \
        : "r"((a)[0]), "r"((a)[1]), "r"((a)[2]), "r"((a)[3]), "r"(b0), "r"(b1))

static __device__ __forceinline__ uint32_t packhl(float v) {
    __nv_bfloat16 h = __float2bfloat16(v);
    __nv_bfloat16 lo = __float2bfloat16(v - __bfloat162float(h));
    return ((uint32_t)__bfloat16_as_ushort(h) << 16) | __bfloat16_as_ushort(lo);
}

// ---- f32x2 helpers for proj ----
__device__ __forceinline__ unsigned long long pk2(float a, float b) {
    unsigned long long r;
    asm("mov.b64 %0, {%1, %2};" : "=l"(r) : "r"(__float_as_uint(a)), "r"(__float_as_uint(b)));
    return r;
}
__device__ __forceinline__ float2 upk2(unsigned long long v) {
    unsigned int lo, hi;
    asm("mov.b64 {%0, %1}, %2;" : "=r"(lo), "=r"(hi) : "l"(v));
    return make_float2(__uint_as_float(lo), __uint_as_float(hi));
}
__device__ __forceinline__ unsigned long long ffma2(unsigned long long a,
                                                    unsigned long long b,
                                                    unsigned long long c) {
    unsigned long long d;
    asm("fma.rn.f32x2 %0, %1, %2, %3;" : "=l"(d) : "l"(a), "l"(b), "l"(c));
    return d;
}

__global__ void init_kernel(const float* __restrict__ taus) {
    int idx = blockIdx.x * blockDim.x + threadIdx.x;
    if (idx < NB * NH) { g_h32[0][idx] = 0.0f; g_hpk[0][idx] = 0u; }
    if (idx < NH) {
        float s = 1.0f / (1.0f + expf(-taus[idx]));
        g_alpha[idx] = 10.0f / (s * 90.0f + 10.0f);
    }
    if (idx < NTILE) { g_cnt[idx] = 0; g_ecnt[idx] = 0; }
}

// transpose in_w [H][I] -> g_wt [I][H]
__global__ void transpose_kernel(const float* __restrict__ w) {
    __shared__ float t[32][33];
    int bi = blockIdx.x * 32;
    int bh = blockIdx.y * 32;
    int tx = threadIdx.x, ty = threadIdx.y;
    for (int i = ty; i < 32; i += 8) t[i][tx] = w[(bh + i) * NI + bi + tx];
    __syncthreads();
    for (int i = ty; i < 32; i += 8) g_wt[(bi + i) * NH + bh + tx] = t[tx][i];
}

// W [k][j] -> g_wthi/g_wtlo [j][k] bf16 split
__global__ void wsplit_kernel(const float* __restrict__ W) {
    __shared__ float t[32][33];
    int bk = blockIdx.x * 32;
    int bj = blockIdx.y * 32;
    int tx = threadIdx.x, ty = threadIdx.y;
    for (int i = ty; i < 32; i += 8) t[i][tx] = W[(bk + i) * NH + bj + tx];
    __syncthreads();
    for (int i = ty; i < 32; i += 8) {
        float v = t[tx][i];
        __nv_bfloat16 hi = __float2bfloat16(v);
        float r = v - __bfloat162float(hi);
        g_wthi[(bj + i) * NH + bk + tx] = hi;
        g_wtlo[(bj + i) * NH + bk + tx] = __float2bfloat16(r);
    }
}

// ---------------------------------------------------------------------------
// Input projection (FFMA2, unchanged)
// ---------------------------------------------------------------------------
__global__ void __launch_bounds__(256) proj_kernel(
    const float* __restrict__ x, const float* __restrict__ bias,
    const float* __restrict__ eps, float* __restrict__ out)
{
    __shared__ float xs[64][20];
    __shared__ float ws[16][68];
    const int tid = threadIdx.x;
    const int rg = tid >> 4, cg = tid & 15;
    const int r4 = rg << 2, c4 = cg << 2;
    const int j0 = blockIdx.x * 64;
    const int r0 = blockIdx.y * 64;
    const int lr = tid >> 2, lk = (tid & 3) << 2;
    const int wk = tid >> 4, wj = (tid & 15) << 2;

    unsigned long long acc[4][2];
#pragma unroll
    for (int i = 0; i < 4; i++) { acc[i][0] = 0ull; acc[i][1] = 0ull; }

    for (int k0 = 0; k0 < NI; k0 += 16) {
        *(float4*)&xs[lr][lk] = *(const float4*)(x + (r0 + lr) * NI + k0 + lk);
        *(float4*)&ws[wk][wj] = *(const float4*)(g_wt + (k0 + wk) * NH + j0 + wj);
        __syncthreads();
#pragma unroll
        for (int k = 0; k < 16; k += 4) {
            ulonglong2 b0 = *(const ulonglong2*)&ws[k + 0][c4];
            ulonglong2 b1 = *(const ulonglong2*)&ws[k + 1][c4];
            ulonglong2 b2 = *(const ulonglong2*)&ws[k + 2][c4];
            ulonglong2 b3 = *(const ulonglong2*)&ws[k + 3][c4];
#pragma unroll
            for (int i = 0; i < 4; i++) {
                float4 a = *(const float4*)&xs[r4 + i][k];
                unsigned long long p;
                p = pk2(a.x, a.x); acc[i][0] = ffma2(p, b0.x, acc[i][0]); acc[i][1] = ffma2(p, b0.y, acc[i][1]);
                p = pk2(a.y, a.y); acc[i][0] = ffma2(p, b1.x, acc[i][0]); acc[i][1] = ffma2(p, b1.y, acc[i][1]);
                p = pk2(a.z, a.z); acc[i][0] = ffma2(p, b2.x, acc[i][0]); acc[i][1] = ffma2(p, b2.y, acc[i][1]);
                p = pk2(a.w, a.w); acc[i][0] = ffma2(p, b3.x, acc[i][0]); acc[i][1] = ffma2(p, b3.y, acc[i][1]);
            }
        }
        __syncthreads();
    }

    float4 bi = *(const float4*)(bias + j0 + c4);
#pragma unroll
    for (int i = 0; i < 4; i++) {
        int r = r0 + r4 + i;
        int off = r * NH + j0 + c4;
        float4 ev = *(const float4*)(eps + off);
        float2 lo = upk2(acc[i][0]);
        float2 hi = upk2(acc[i][1]);
        float4 o;
        o.x = lo.x + bi.x + NOISEF * ev.x;
        o.y = lo.y + bi.y + NOISEF * ev.y;
        o.z = hi.x + bi.z + NOISEF * ev.z;
        o.w = hi.y + bi.w + NOISEF * ev.w;
        *(float4*)(out + off) = o;
    }
}

// ---------------------------------------------------------------------------
// Persistent scan: 128 blocks (nt, ks), point-to-point sync via per-tile
// monotonic counters. HMMA split-bf16 GEMM (R6 core).
// ---------------------------------------------------------------------------
__global__ void __launch_bounds__(256) scan_kernel(float* __restrict__ out)
{
    extern __shared__ char smem[];
    const uint32_t sb = smem_u32(smem);
    const int tid = threadIdx.x;
    const int l = tid & 31, w = tid >> 5;
    const int nt = blockIdx.x & 15;
    const int ks = blockIdx.x >> 4;
    const int j0 = nt * 64;
    const int k0 = ks * 128;

    // Load W^T hi/lo tile [64 j][128 k] into padded smem (once)
    {
        int r = tid >> 2, c = tid & 3;
        const uint4* sh = (const uint4*)(g_wthi + (size_t)(j0 + r) * NH + k0) + c * 4;
        const uint4* sl = (const uint4*)(g_wtlo + (size_t)(j0 + r) * NH + k0) + c * 4;
        char* dh = smem + SM_WHI + r * ROWB + c * 64;
        char* dl = smem + SM_WLO + r * ROWB + c * 64;
#pragma unroll
        for (int i = 0; i < 4; i++) {
            *(uint4*)(dh + i * 16) = sh[i];
            *(uint4*)(dl + i * 16) = sl[i];
        }
    }

    // ldmatrix per-lane addresses (R6 mapping)
    const int wm = (w & 3) * 16;    // j offset of warp
    const int wn = (w >> 2) * 32;   // b offset of warp
    const uint32_t aHi = sb + SM_WHI + (wm + (l & 15)) * ROWB + (l >> 4) * 16;
    const uint32_t aLo = aHi + (SM_WLO - SM_WHI);
    const uint32_t brow = wn + ((l >> 4) << 3) + (l & 7);
    const uint32_t boff = ((l >> 3) & 1) * 16;
    const uint32_t b0Hi = sb + SM_BHI + brow * ROWB + boff;
    const uint32_t b1Hi = b0Hi + 16 * ROWB;
    const uint32_t b0Lo = b0Hi + (SM_BLO - SM_BHI);
    const uint32_t b1Lo = b1Hi + (SM_BLO - SM_BHI);

    // slab-store coords (slab layout [b][NH])
    const int sj0 = j0 + wm + (l >> 2);
    const int sb0 = wn + 2 * (l & 3);

    // epilogue coords: rows b in [8ks, 8ks+8), cols = tile nt (64 j)
    const int ej = j0 + (tid & 63);
    const int eb = 8 * ks + 2 * (tid >> 6);
    const float alf = g_alpha[ej];

    // staging coords (R6)
    const int stb = tid >> 2, stc = tid & 3;
    char* dBh = smem + SM_BHI + stb * ROWB + stc * 64;
    char* dBl = smem + SM_BLO + stb * ROWB + stc * 64;

    __syncthreads();

    for (int t = 0; t < TT; t++) {
        // point-to-point waits (3 warps poll in parallel)
        if (t > 0) {
            const int tgt = 8 * t;
            if (tid == 0)  { while (__ldcg(&g_ecnt[2 * ks]) < tgt) __nanosleep(16); }
            if (tid == 32) { while (__ldcg(&g_ecnt[2 * ks + 1]) < tgt) __nanosleep(16); }
            if (tid == 64) { while (__ldcg(&g_ecnt[nt]) < tgt) __nanosleep(16); }
            __syncthreads();
        }

        // stage h slice: unpack packed hi|lo -> bf16 smem tiles
        const unsigned int* hsrc = g_hpk[t & 1];
        {
            const uint4* src = (const uint4*)(hsrc + stb * NH + k0) + stc * 8;
#pragma unroll
            for (int i = 0; i < 8; i++) {
                uint4 v = __ldcg(src + i);
                uint32_t h0 = __byte_perm(v.x, v.y, 0x7632);
                uint32_t l0 = __byte_perm(v.x, v.y, 0x5410);
                uint32_t h1 = __byte_perm(v.z, v.w, 0x7632);
                uint32_t l1 = __byte_perm(v.z, v.w, 0x5410);
                *(uint2*)(dBh + i * 8) = make_uint2(h0, h1);
                *(uint2*)(dBl + i * 8) = make_uint2(l0, l1);
            }
        }
        __syncthreads();

        // GEMM: 8 k-steps of 16, split-bf16 (3 products), HMMA
        float acc[4][4];
#pragma unroll
        for (int n = 0; n < 4; n++)
#pragma unroll
            for (int i = 0; i < 4; i++) acc[n][i] = 0.0f;

#pragma unroll
        for (int kk = 0; kk < 8; kk++) {
            const uint32_t off = kk * 32;
            uint32_t ah[4], al4[4], bh0[4], bh1[4], bl0[4], bl1[4];
            LDSM4(ah, aHi + off);
            LDSM4(al4, aLo + off);
            LDSM4(bh0, b0Hi + off);
            LDSM4(bh1, b1Hi + off);
            LDSM4(bl0, b0Lo + off);
            LDSM4(bl1, b1Lo + off);
            MMA16816(acc[0], ah, bh0[0], bh0[1]);
            MMA16816(acc[1], ah, bh0[2], bh0[3]);
            MMA16816(acc[2], ah, bh1[0], bh1[1]);
            MMA16816(acc[3], ah, bh1[2], bh1[3]);
            MMA16816(acc[0], ah, bl0[0], bl0[1]);
            MMA16816(acc[1], ah, bl0[2], bl0[3]);
            MMA16816(acc[2], ah, bl1[0], bl1[1]);
            MMA16816(acc[3], ah, bl1[2], bl1[3]);
            MMA16816(acc[0], al4, bh0[0], bh0[1]);
            MMA16816(acc[1], al4, bh0[2], bh0[3]);
            MMA16816(acc[2], al4, bh1[0], bh1[1]);
            MMA16816(acc[3], al4, bh1[2], bh1[3]);
        }

        // store slab, layout [b][NH]
        {
            float* part = g_part[ks];
#pragma unroll
            for (int n = 0; n < 4; n++) {
                int b = sb0 + n * 8;
                part[(size_t)b * NH + sj0] = acc[n][0];
                part[(size_t)(b + 1) * NH + sj0] = acc[n][1];
                part[(size_t)b * NH + sj0 + 8] = acc[n][2];
                part[(size_t)(b + 1) * NH + sj0 + 8] = acc[n][3];
            }
        }

        // prefetch epilogue operands (independent of slabs)
        const long o0 = ((long)eb * TT + t) * NH + ej;
        const long o1 = o0 + (long)TT * NH;
        const float p0 = out[o0];
        const float p1 = out[o1];
        const float* hin32 = g_h32[t & 1];
        const float h0 = hin32[eb * NH + ej];
        const float h1 = hin32[(eb + 1) * NH + ej];

        __threadfence();
        __syncthreads();
        if (tid == 0) {
            atomicAdd(&g_cnt[nt], 1);
            while (__ldcg(&g_cnt[nt]) < 8 * (t + 1)) __nanosleep(16);
        }
        __syncthreads();

        // distributed epilogue: sum 8 slabs (fixed order), coalesced in j
        {
            float s0 = 0.0f, s1 = 0.0f;
#pragma unroll
            for (int q = 0; q < NKS; q++) {
                s0 += __ldcg(&g_part[q][(size_t)eb * NH + ej]);
                s1 += __ldcg(&g_part[q][(size_t)(eb + 1) * NH + ej]);
            }
            float n0 = (1.0f - alf) * h0 + alf * tanhf(p0 + s0);
            float n1 = (1.0f - alf) * h1 + alf * tanhf(p1 + s1);
            out[o0] = n0;
            out[o1] = n1;
            float* h32o = g_h32[(t + 1) & 1];
            unsigned int* hpko = g_hpk[(t + 1) & 1];
            h32o[eb * NH + ej] = n0;
            h32o[(eb + 1) * NH + ej] = n1;
            hpko[eb * NH + ej] = packhl(n0);
            hpko[(eb + 1) * NH + ej] = packhl(n1);
        }

        __threadfence();
        __syncthreads();
        if (tid == 0) atomicAdd(&g_ecnt[nt], 1);
    }
}

extern "C" void kernel_launch(void* const* d_in, const int* in_sizes, int n_in,
                              void* d_out, int out_size) {
    const float* x    = (const float*)d_in[0];  // [B,T,I]
    const float* eps  = (const float*)d_in[1];  // [B,T,H]
    const float* in_w = (const float*)d_in[2];  // [H,I]
    const float* in_b = (const float*)d_in[3];  // [H]
    const float* W    = (const float*)d_in[4];  // [H,H]
    const float* taus = (const float*)d_in[5];  // [H]
    float* out = (float*)d_out;                 // [B,T,H]

    static int attr_done = 0;
    if (!attr_done) {
        cudaFuncSetAttribute(scan_kernel, cudaFuncAttributeMaxDynamicSharedMemorySize, SM_TOTAL);
        attr_done = 1;
    }

    init_kernel<<<(NB * NH + 255) / 256, 256>>>(taus);
    transpose_kernel<<<dim3(NI / 32, NH / 32), dim3(32, 8)>>>(in_w);
    wsplit_kernel<<<dim3(NH / 32, NH / 32), dim3(32, 8)>>>(W);

    dim3 pgrid(NH / 64, (NB * TT) / 64);
    proj_kernel<<<pgrid, 256>>>(x, in_b, eps, out);

    scan_kernel<<<NBLK, 256, SM_TOTAL>>>(out);
}

// round 10
// speedup vs baseline: 2.1655x; 1.1085x over previous
#include <cuda_runtime.h>
#include <cuda_bf16.h>
#include <math.h>
#include <stdint.h>

#define NB 64
#define TT 512
#define NI 256
#define NH 1024
#define NOISEF 0.1f
#define NKS 8             // k-slices of 128
#define NTILE 16          // j-tiles of 64
#define NBLK 128

// ---- static device scratch ----
__device__ float g_h32[2][NB * NH];          // fp32 hidden state [b][j], double buf
__device__ unsigned int g_hpk[2][NB * NH];   // packed bf16 hi<<16|lo of h
__device__ float g_part[NKS][NB * NH];       // split-K slabs, layout [b][j]
__device__ float g_alpha[NH];
__device__ float g_wt[NI * NH];              // transposed in_w for proj (f32)
__device__ __nv_bfloat16 g_wthi[NH * NH];    // [j][k] = bf16_hi(W[k][j])
__device__ __nv_bfloat16 g_wtlo[NH * NH];    // [j][k] = residual
__device__ int g_cnt[NTILE];                 // slab arrivals per tile (monotonic)
__device__ int g_ecnt[NTILE];                // epilogue parts per tile (monotonic)

// smem layout (272B-padded rows of 128 bf16 for conflict-free ldmatrix)
#define SM_WHI 0
#define SM_WLO 17408
#define SM_BHI 34816
#define SM_BLO 52224
#define SM_TOTAL 69632
#define ROWB 272

static __device__ __forceinline__ uint32_t smem_u32(const void* p) {
    uint32_t a;
    asm("{ .reg .u64 t; cvta.to.shared.u64 t, %1; cvt.u32.u64 %0, t; }" : "=r"(a) : "l"(p));
    return a;
}
// volatile L2 poll load — cannot be CSE'd/hoisted by the compiler
static __device__ __forceinline__ int ldpoll(const int* p) {
    int v;
    asm volatile("ld.global.cg.b32 %0, [%1];" : "=r"(v) : "l"(p) : "memory");
    return v;
}

#define LDSM4(r, a)                                                             \
    asm volatile("ldmatrix.sync.aligned.m8n8.x4.shared.b16 {%0,%1,%2,%3}, [%4];" \
        : "=r"((r)[0]), "=r"((r)[1]), "=r"((r)[2]), "=r"((r)[3]) : "r"(a))

#define MMA16816(d, a, b0, b1)                                                  \
    asm volatile("mma.sync.aligned.m16n8k16.row.col.f32.bf16.bf16.f32 "         \
        "{%0,%1,%2,%3}, {%4,%5,%6,%7}, {%8,%9}, {%0,%1,%2,%3};"                 \
        : "+f"((d)[0]), "+f"((d)[1]), "+f"((d)[2]), "+f"((d)[3])                \
        : "r"((a)[0]), "r"((a)[1]), "r"((a)[2]), "r"((a)[3]), "r"(b0), "r"(b1))

static __device__ __forceinline__ uint32_t packhl(float v) {
    __nv_bfloat16 h = __float2bfloat16(v);
    __nv_bfloat16 lo = __float2bfloat16(v - __bfloat162float(h));
    return ((uint32_t)__bfloat16_as_ushort(h) << 16) | __bfloat16_as_ushort(lo);
}
// fast tanh: exp-based, ~1e-6 abs error; correct saturation
static __device__ __forceinline__ float ftanh(float x) {
    float e = __expf(2.0f * x);
    return 1.0f - __fdividef(2.0f, e + 1.0f);
}

// ---- f32x2 helpers for proj ----
__device__ __forceinline__ unsigned long long pk2(float a, float b) {
    unsigned long long r;
    asm("mov.b64 %0, {%1, %2};" : "=l"(r) : "r"(__float_as_uint(a)), "r"(__float_as_uint(b)));
    return r;
}
__device__ __forceinline__ float2 upk2(unsigned long long v) {
    unsigned int lo, hi;
    asm("mov.b64 {%0, %1}, %2;" : "=r"(lo), "=r"(hi) : "l"(v));
    return make_float2(__uint_as_float(lo), __uint_as_float(hi));
}
__device__ __forceinline__ unsigned long long ffma2(unsigned long long a,
                                                    unsigned long long b,
                                                    unsigned long long c) {
    unsigned long long d;
    asm("fma.rn.f32x2 %0, %1, %2, %3;" : "=l"(d) : "l"(a), "l"(b), "l"(c));
    return d;
}

__global__ void init_kernel(const float* __restrict__ taus) {
    int idx = blockIdx.x * blockDim.x + threadIdx.x;
    if (idx < NB * NH) { g_h32[0][idx] = 0.0f; g_hpk[0][idx] = 0u; }
    if (idx < NH) {
        float s = 1.0f / (1.0f + expf(-taus[idx]));
        g_alpha[idx] = 10.0f / (s * 90.0f + 10.0f);
    }
    if (idx < NTILE) { g_cnt[idx] = 0; g_ecnt[idx] = 0; }
}

// transpose in_w [H][I] -> g_wt [I][H]
__global__ void transpose_kernel(const float* __restrict__ w) {
    __shared__ float t[32][33];
    int bi = blockIdx.x * 32;
    int bh = blockIdx.y * 32;
    int tx = threadIdx.x, ty = threadIdx.y;
    for (int i = ty; i < 32; i += 8) t[i][tx] = w[(bh + i) * NI + bi + tx];
    __syncthreads();
    for (int i = ty; i < 32; i += 8) g_wt[(bi + i) * NH + bh + tx] = t[tx][i];
}

// W [k][j] -> g_wthi/g_wtlo [j][k] bf16 split
__global__ void wsplit_kernel(const float* __restrict__ W) {
    __shared__ float t[32][33];
    int bk = blockIdx.x * 32;
    int bj = blockIdx.y * 32;
    int tx = threadIdx.x, ty = threadIdx.y;
    for (int i = ty; i < 32; i += 8) t[i][tx] = W[(bk + i) * NH + bj + tx];
    __syncthreads();
    for (int i = ty; i < 32; i += 8) {
        float v = t[tx][i];
        __nv_bfloat16 hi = __float2bfloat16(v);
        float r = v - __bfloat162float(hi);
        g_wthi[(bj + i) * NH + bk + tx] = hi;
        g_wtlo[(bj + i) * NH + bk + tx] = __float2bfloat16(r);
    }
}

// ---------------------------------------------------------------------------
// Input projection (FFMA2, unchanged)
// ---------------------------------------------------------------------------
__global__ void __launch_bounds__(256) proj_kernel(
    const float* __restrict__ x, const float* __restrict__ bias,
    const float* __restrict__ eps, float* __restrict__ out)
{
    __shared__ float xs[64][20];
    __shared__ float ws[16][68];
    const int tid = threadIdx.x;
    const int rg = tid >> 4, cg = tid & 15;
    const int r4 = rg << 2, c4 = cg << 2;
    const int j0 = blockIdx.x * 64;
    const int r0 = blockIdx.y * 64;
    const int lr = tid >> 2, lk = (tid & 3) << 2;
    const int wk = tid >> 4, wj = (tid & 15) << 2;

    unsigned long long acc[4][2];
#pragma unroll
    for (int i = 0; i < 4; i++) { acc[i][0] = 0ull; acc[i][1] = 0ull; }

    for (int k0 = 0; k0 < NI; k0 += 16) {
        *(float4*)&xs[lr][lk] = *(const float4*)(x + (r0 + lr) * NI + k0 + lk);
        *(float4*)&ws[wk][wj] = *(const float4*)(g_wt + (k0 + wk) * NH + j0 + wj);
        __syncthreads();
#pragma unroll
        for (int k = 0; k < 16; k += 4) {
            ulonglong2 b0 = *(const ulonglong2*)&ws[k + 0][c4];
            ulonglong2 b1 = *(const ulonglong2*)&ws[k + 1][c4];
            ulonglong2 b2 = *(const ulonglong2*)&ws[k + 2][c4];
            ulonglong2 b3 = *(const ulonglong2*)&ws[k + 3][c4];
#pragma unroll
            for (int i = 0; i < 4; i++) {
                float4 a = *(const float4*)&xs[r4 + i][k];
                unsigned long long p;
                p = pk2(a.x, a.x); acc[i][0] = ffma2(p, b0.x, acc[i][0]); acc[i][1] = ffma2(p, b0.y, acc[i][1]);
                p = pk2(a.y, a.y); acc[i][0] = ffma2(p, b1.x, acc[i][0]); acc[i][1] = ffma2(p, b1.y, acc[i][1]);
                p = pk2(a.z, a.z); acc[i][0] = ffma2(p, b2.x, acc[i][0]); acc[i][1] = ffma2(p, b2.y, acc[i][1]);
                p = pk2(a.w, a.w); acc[i][0] = ffma2(p, b3.x, acc[i][0]); acc[i][1] = ffma2(p, b3.y, acc[i][1]);
            }
        }
        __syncthreads();
    }

    float4 bi = *(const float4*)(bias + j0 + c4);
#pragma unroll
    for (int i = 0; i < 4; i++) {
        int r = r0 + r4 + i;
        int off = r * NH + j0 + c4;
        float4 ev = *(const float4*)(eps + off);
        float2 lo = upk2(acc[i][0]);
        float2 hi = upk2(acc[i][1]);
        float4 o;
        o.x = lo.x + bi.x + NOISEF * ev.x;
        o.y = lo.y + bi.y + NOISEF * ev.y;
        o.z = hi.x + bi.z + NOISEF * ev.z;
        o.w = hi.y + bi.w + NOISEF * ev.w;
        *(float4*)(out + off) = o;
    }
}

// ---------------------------------------------------------------------------
// Persistent scan: 128 blocks (nt, ks), point-to-point sync (volatile polls),
// HMMA split-bf16 GEMM with A (W) fragments hoisted into registers.
// ---------------------------------------------------------------------------
__global__ void __launch_bounds__(256, 1) scan_kernel(float* __restrict__ out)
{
    extern __shared__ char smem[];
    const uint32_t sb = smem_u32(smem);
    const int tid = threadIdx.x;
    const int l = tid & 31, w = tid >> 5;
    const int nt = blockIdx.x & 15;
    const int ks = blockIdx.x >> 4;
    const int j0 = nt * 64;
    const int k0 = ks * 128;

    // Load W^T hi/lo tile [64 j][128 k] into padded smem (once)
    {
        int r = tid >> 2, c = tid & 3;
        const uint4* sh = (const uint4*)(g_wthi + (size_t)(j0 + r) * NH + k0) + c * 4;
        const uint4* sl = (const uint4*)(g_wtlo + (size_t)(j0 + r) * NH + k0) + c * 4;
        char* dh = smem + SM_WHI + r * ROWB + c * 64;
        char* dl = smem + SM_WLO + r * ROWB + c * 64;
#pragma unroll
        for (int i = 0; i < 4; i++) {
            *(uint4*)(dh + i * 16) = sh[i];
            *(uint4*)(dl + i * 16) = sl[i];
        }
    }

    // lane addresses
    const int wm = (w & 3) * 16;    // j offset of warp
    const int wn = (w >> 2) * 32;   // b offset of warp
    const uint32_t aHi = sb + SM_WHI + (wm + (l & 15)) * ROWB + (l >> 4) * 16;
    const uint32_t aLo = aHi + (SM_WLO - SM_WHI);
    const uint32_t brow = wn + ((l >> 4) << 3) + (l & 7);
    const uint32_t boff = ((l >> 3) & 1) * 16;
    const uint32_t b0Hi = sb + SM_BHI + brow * ROWB + boff;
    const uint32_t b1Hi = b0Hi + 16 * ROWB;
    const uint32_t b0Lo = b0Hi + (SM_BLO - SM_BHI);
    const uint32_t b1Lo = b1Hi + (SM_BLO - SM_BHI);

    __syncthreads();

    // Hoist A fragments (W tile) into registers: loop-invariant across t
    uint32_t Ah[8][4], Al[8][4];
#pragma unroll
    for (int kk = 0; kk < 8; kk++) {
        LDSM4(Ah[kk], aHi + kk * 32);
        LDSM4(Al[kk], aLo + kk * 32);
    }

    // slab-store coords (slab layout [b][NH])
    const int sj0 = j0 + wm + (l >> 2);
    const int sb0 = wn + 2 * (l & 3);

    // epilogue coords: rows b in [8ks, 8ks+8), cols = tile nt (64 j)
    const int ej = j0 + (tid & 63);
    const int eb = 8 * ks + 2 * (tid >> 6);
    const float alf = g_alpha[ej];

    // staging coords
    const int stb = tid >> 2, stc = tid & 3;
    char* dBh = smem + SM_BHI + stb * ROWB + stc * 64;
    char* dBl = smem + SM_BLO + stb * ROWB + stc * 64;

    for (int t = 0; t < TT; t++) {
        // point-to-point waits (3 warps poll in parallel, volatile loads)
        if (t > 0) {
            const int tgt = 8 * t;
            if (tid == 0)  { while (ldpoll(&g_ecnt[2 * ks]) < tgt) __nanosleep(16); }
            if (tid == 32) { while (ldpoll(&g_ecnt[2 * ks + 1]) < tgt) __nanosleep(16); }
            if (tid == 64) { while (ldpoll(&g_ecnt[nt]) < tgt) __nanosleep(16); }
            __syncthreads();
        }

        // stage h slice: unpack packed hi|lo -> bf16 smem tiles
        const unsigned int* hsrc = g_hpk[t & 1];
        {
            const uint4* src = (const uint4*)(hsrc + stb * NH + k0) + stc * 8;
#pragma unroll
            for (int i = 0; i < 8; i++) {
                uint4 v = __ldcg(src + i);
                uint32_t h0 = __byte_perm(v.x, v.y, 0x7632);
                uint32_t l0 = __byte_perm(v.x, v.y, 0x5410);
                uint32_t h1 = __byte_perm(v.z, v.w, 0x7632);
                uint32_t l1 = __byte_perm(v.z, v.w, 0x5410);
                *(uint2*)(dBh + i * 8) = make_uint2(h0, h1);
                *(uint2*)(dBl + i * 8) = make_uint2(l0, l1);
            }
        }

        // prefetch epilogue operands early: GEMM hides their latency.
        // Safe: out rows and g_h32[t&1] rows for tile nt were finalized before
        // the ecnt waits above.
        const long o0 = ((long)eb * TT + t) * NH + ej;
        const long o1 = o0 + (long)TT * NH;
        const float p0 = out[o0];
        const float p1 = out[o1];
        const float* hin32 = g_h32[t & 1];
        const float h0 = __ldcg(&hin32[eb * NH + ej]);
        const float h1 = __ldcg(&hin32[(eb + 1) * NH + ej]);

        __syncthreads();

        // GEMM: 8 k-steps of 16, split-bf16 (3 products), A in registers
        float acc[4][4];
#pragma unroll
        for (int n = 0; n < 4; n++)
#pragma unroll
            for (int i = 0; i < 4; i++) acc[n][i] = 0.0f;

#pragma unroll
        for (int kk = 0; kk < 8; kk++) {
            const uint32_t off = kk * 32;
            uint32_t bh0[4], bh1[4], bl0[4], bl1[4];
            LDSM4(bh0, b0Hi + off);
            LDSM4(bh1, b1Hi + off);
            LDSM4(bl0, b0Lo + off);
            LDSM4(bl1, b1Lo + off);
            MMA16816(acc[0], Ah[kk], bh0[0], bh0[1]);
            MMA16816(acc[1], Ah[kk], bh0[2], bh0[3]);
            MMA16816(acc[2], Ah[kk], bh1[0], bh1[1]);
            MMA16816(acc[3], Ah[kk], bh1[2], bh1[3]);
            MMA16816(acc[0], Ah[kk], bl0[0], bl0[1]);
            MMA16816(acc[1], Ah[kk], bl0[2], bl0[3]);
            MMA16816(acc[2], Ah[kk], bl1[0], bl1[1]);
            MMA16816(acc[3], Ah[kk], bl1[2], bl1[3]);
            MMA16816(acc[0], Al[kk], bh0[0], bh0[1]);
            MMA16816(acc[1], Al[kk], bh0[2], bh0[3]);
            MMA16816(acc[2], Al[kk], bh1[0], bh1[1]);
            MMA16816(acc[3], Al[kk], bh1[2], bh1[3]);
        }

        // store slab, layout [b][NH]
        {
            float* part = g_part[ks];
#pragma unroll
            for (int n = 0; n < 4; n++) {
                int b = sb0 + n * 8;
                part[(size_t)b * NH + sj0] = acc[n][0];
                part[(size_t)(b + 1) * NH + sj0] = acc[n][1];
                part[(size_t)b * NH + sj0 + 8] = acc[n][2];
                part[(size_t)(b + 1) * NH + sj0 + 8] = acc[n][3];
            }
        }

        __threadfence();
        __syncthreads();
        if (tid == 0) {
            atomicAdd(&g_cnt[nt], 1);
            while (ldpoll(&g_cnt[nt]) < 8 * (t + 1)) __nanosleep(16);
        }
        __syncthreads();

        // distributed epilogue: sum 8 slabs (fixed order), coalesced in j
        {
            float s0 = 0.0f, s1 = 0.0f;
#pragma unroll
            for (int q = 0; q < NKS; q++) {
                s0 += __ldcg(&g_part[q][(size_t)eb * NH + ej]);
                s1 += __ldcg(&g_part[q][(size_t)(eb + 1) * NH + ej]);
            }
            float n0 = (1.0f - alf) * h0 + alf * ftanh(p0 + s0);
            float n1 = (1.0f - alf) * h1 + alf * ftanh(p1 + s1);
            out[o0] = n0;
            out[o1] = n1;
            float* h32o = g_h32[(t + 1) & 1];
            unsigned int* hpko = g_hpk[(t + 1) & 1];
            h32o[eb * NH + ej] = n0;
            h32o[(eb + 1) * NH + ej] = n1;
            hpko[eb * NH + ej] = packhl(n0);
            hpko[(eb + 1) * NH + ej] = packhl(n1);
        }

        __threadfence();
        __syncthreads();
        if (tid == 0) atomicAdd(&g_ecnt[nt], 1);
    }
}

extern "C" void kernel_launch(void* const* d_in, const int* in_sizes, int n_in,
                              void* d_out, int out_size) {
    const float* x    = (const float*)d_in[0];  // [B,T,I]
    const float* eps  = (const float*)d_in[1];  // [B,T,H]
    const float* in_w = (const float*)d_in[2];  // [H,I]
    const float* in_b = (const float*)d_in[3];  // [H]
    const float* W    = (const float*)d_in[4];  // [H,H]
    const float* taus = (const float*)d_in[5];  // [H]
    float* out = (float*)d_out;                 // [B,T,H]

    static int attr_done = 0;
    if (!attr_done) {
        cudaFuncSetAttribute(scan_kernel, cudaFuncAttributeMaxDynamicSharedMemorySize, SM_TOTAL);
        attr_done = 1;
    }

    init_kernel<<<(NB * NH + 255) / 256, 256>>>(taus);
    transpose_kernel<<<dim3(NI / 32, NH / 32), dim3(32, 8)>>>(in_w);
    wsplit_kernel<<<dim3(NH / 32, NH / 32), dim3(32, 8)>>>(W);

    dim3 pgrid(NH / 64, (NB * TT) / 64);
    proj_kernel<<<pgrid, 256>>>(x, in_b, eps, out);

    scan_kernel<<<NBLK, 256, SM_TOTAL>>>(out);
}

// round 11
// speedup vs baseline: 2.3225x; 1.0725x over previous
#include <cuda_runtime.h>
#include <cuda_bf16.h>
#include <math.h>
#include <stdint.h>

#define NB 64
#define TT 512
#define NI 256
#define NH 1024
#define NOISEF 0.1f
#define NKS 8             // k-slices of 128
#define NTILE 16          // j-tiles of 64
#define NBLK 128

// ---- static device scratch ----
__device__ float g_h32[2][NB * NH];          // fp32 hidden state [b][j], double buf
__device__ unsigned int g_hpk[2][NB * NH];   // packed bf16 hi<<16|lo of h
__device__ float g_part[NKS][NB * NH];       // split-K slabs, PAIR layout [b/2][j][2]
__device__ float g_alpha[NH];
__device__ float g_wt[NI * NH];              // transposed in_w for proj (f32)
__device__ __nv_bfloat16 g_wthi[NH * NH];    // [j][k] = bf16_hi(W[k][j])
__device__ __nv_bfloat16 g_wtlo[NH * NH];    // [j][k] = residual
__device__ int g_cnt[NTILE];                 // slab arrivals per tile (monotonic)
__device__ int g_ecnt[NTILE];                // epilogue parts per tile (monotonic)

// smem layout (272B-padded rows of 128 bf16 for conflict-free ldmatrix)
#define SM_WHI 0
#define SM_WLO 17408
#define SM_BHI 34816
#define SM_BLO 52224
#define SM_TOTAL 69632
#define ROWB 272

static __device__ __forceinline__ uint32_t smem_u32(const void* p) {
    uint32_t a;
    asm("{ .reg .u64 t; cvta.to.shared.u64 t, %1; cvt.u32.u64 %0, t; }" : "=r"(a) : "l"(p));
    return a;
}
// acquire poll load (gpu scope) — cannot be hoisted, orders subsequent reads
static __device__ __forceinline__ int ldacq(const int* p) {
    int v;
    asm volatile("ld.acquire.gpu.global.b32 %0, [%1];" : "=r"(v) : "l"(p) : "memory");
    return v;
}
// release increment (gpu scope) — orders all prior memory ops of this thread
// (and, via preceding bar.sync, of the whole CTA) before the counter bump
static __device__ __forceinline__ void red_rel(int* p) {
    asm volatile("red.release.gpu.global.add.s32 [%0], 1;" :: "l"(p) : "memory");
}

#define LDSM4(r, a)                                                             \
    asm volatile("ldmatrix.sync.aligned.m8n8.x4.shared.b16 {%0,%1,%2,%3}, [%4];" \
        : "=r"((r)[0]), "=r"((r)[1]), "=r"((r)[2]), "=r"((r)[3]) : "r"(a))

#define MMA16816(d, a, b0, b1)                                                  \
    asm volatile("mma.sync.aligned.m16n8k16.row.col.f32.bf16.bf16.f32 "         \
        "{%0,%1,%2,%3}, {%4,%5,%6,%7}, {%8,%9}, {%0,%1,%2,%3};"                 \
        : "+f"((d)[0]), "+f"((d)[1]), "+f"((d)[2]), "+f"((d)[3])                \
        : "r"((a)[0]), "r"((a)[1]), "r"((a)[2]), "r"((a)[3]), "r"(b0), "r"(b1))

static __device__ __forceinline__ uint32_t packhl(float v) {
    __nv_bfloat16 h = __float2bfloat16(v);
    __nv_bfloat16 lo = __float2bfloat16(v - __bfloat162float(h));
    return ((uint32_t)__bfloat16_as_ushort(h) << 16) | __bfloat16_as_ushort(lo);
}
// fast tanh: exp-based, ~1e-6 abs error; correct saturation
static __device__ __forceinline__ float ftanh(float x) {
    float e = __expf(2.0f * x);
    return 1.0f - __fdividef(2.0f, e + 1.0f);
}

// ---- f32x2 helpers for proj ----
__device__ __forceinline__ unsigned long long pk2(float a, float b) {
    unsigned long long r;
    asm("mov.b64 %0, {%1, %2};" : "=l"(r) : "r"(__float_as_uint(a)), "r"(__float_as_uint(b)));
    return r;
}
__device__ __forceinline__ float2 upk2(unsigned long long v) {
    unsigned int lo, hi;
    asm("mov.b64 {%0, %1}, %2;" : "=r"(lo), "=r"(hi) : "l"(v));
    return make_float2(__uint_as_float(lo), __uint_as_float(hi));
}
__device__ __forceinline__ unsigned long long ffma2(unsigned long long a,
                                                    unsigned long long b,
                                                    unsigned long long c) {
    unsigned long long d;
    asm("fma.rn.f32x2 %0, %1, %2, %3;" : "=l"(d) : "l"(a), "l"(b), "l"(c));
    return d;
}

__global__ void init_kernel(const float* __restrict__ taus) {
    int idx = blockIdx.x * blockDim.x + threadIdx.x;
    if (idx < NB * NH) { g_h32[0][idx] = 0.0f; g_hpk[0][idx] = 0u; }
    if (idx < NH) {
        float s = 1.0f / (1.0f + expf(-taus[idx]));
        g_alpha[idx] = 10.0f / (s * 90.0f + 10.0f);
    }
    if (idx < NTILE) { g_cnt[idx] = 0; g_ecnt[idx] = 0; }
}

// transpose in_w [H][I] -> g_wt [I][H]
__global__ void transpose_kernel(const float* __restrict__ w) {
    __shared__ float t[32][33];
    int bi = blockIdx.x * 32;
    int bh = blockIdx.y * 32;
    int tx = threadIdx.x, ty = threadIdx.y;
    for (int i = ty; i < 32; i += 8) t[i][tx] = w[(bh + i) * NI + bi + tx];
    __syncthreads();
    for (int i = ty; i < 32; i += 8) g_wt[(bi + i) * NH + bh + tx] = t[tx][i];
}

// W [k][j] -> g_wthi/g_wtlo [j][k] bf16 split
__global__ void wsplit_kernel(const float* __restrict__ W) {
    __shared__ float t[32][33];
    int bk = blockIdx.x * 32;
    int bj = blockIdx.y * 32;
    int tx = threadIdx.x, ty = threadIdx.y;
    for (int i = ty; i < 32; i += 8) t[i][tx] = W[(bk + i) * NH + bj + tx];
    __syncthreads();
    for (int i = ty; i < 32; i += 8) {
        float v = t[tx][i];
        __nv_bfloat16 hi = __float2bfloat16(v);
        float r = v - __bfloat162float(hi);
        g_wthi[(bj + i) * NH + bk + tx] = hi;
        g_wtlo[(bj + i) * NH + bk + tx] = __float2bfloat16(r);
    }
}

// ---------------------------------------------------------------------------
// Input projection (FFMA2, unchanged)
// ---------------------------------------------------------------------------
__global__ void __launch_bounds__(256) proj_kernel(
    const float* __restrict__ x, const float* __restrict__ bias,
    const float* __restrict__ eps, float* __restrict__ out)
{
    __shared__ float xs[64][20];
    __shared__ float ws[16][68];
    const int tid = threadIdx.x;
    const int rg = tid >> 4, cg = tid & 15;
    const int r4 = rg << 2, c4 = cg << 2;
    const int j0 = blockIdx.x * 64;
    const int r0 = blockIdx.y * 64;
    const int lr = tid >> 2, lk = (tid & 3) << 2;
    const int wk = tid >> 4, wj = (tid & 15) << 2;

    unsigned long long acc[4][2];
#pragma unroll
    for (int i = 0; i < 4; i++) { acc[i][0] = 0ull; acc[i][1] = 0ull; }

    for (int k0 = 0; k0 < NI; k0 += 16) {
        *(float4*)&xs[lr][lk] = *(const float4*)(x + (r0 + lr) * NI + k0 + lk);
        *(float4*)&ws[wk][wj] = *(const float4*)(g_wt + (k0 + wk) * NH + j0 + wj);
        __syncthreads();
#pragma unroll
        for (int k = 0; k < 16; k += 4) {
            ulonglong2 b0 = *(const ulonglong2*)&ws[k + 0][c4];
            ulonglong2 b1 = *(const ulonglong2*)&ws[k + 1][c4];
            ulonglong2 b2 = *(const ulonglong2*)&ws[k + 2][c4];
            ulonglong2 b3 = *(const ulonglong2*)&ws[k + 3][c4];
#pragma unroll
            for (int i = 0; i < 4; i++) {
                float4 a = *(const float4*)&xs[r4 + i][k];
                unsigned long long p;
                p = pk2(a.x, a.x); acc[i][0] = ffma2(p, b0.x, acc[i][0]); acc[i][1] = ffma2(p, b0.y, acc[i][1]);
                p = pk2(a.y, a.y); acc[i][0] = ffma2(p, b1.x, acc[i][0]); acc[i][1] = ffma2(p, b1.y, acc[i][1]);
                p = pk2(a.z, a.z); acc[i][0] = ffma2(p, b2.x, acc[i][0]); acc[i][1] = ffma2(p, b2.y, acc[i][1]);
                p = pk2(a.w, a.w); acc[i][0] = ffma2(p, b3.x, acc[i][0]); acc[i][1] = ffma2(p, b3.y, acc[i][1]);
            }
        }
        __syncthreads();
    }

    float4 bi = *(const float4*)(bias + j0 + c4);
#pragma unroll
    for (int i = 0; i < 4; i++) {
        int r = r0 + r4 + i;
        int off = r * NH + j0 + c4;
        float4 ev = *(const float4*)(eps + off);
        float2 lo = upk2(acc[i][0]);
        float2 hi = upk2(acc[i][1]);
        float4 o;
        o.x = lo.x + bi.x + NOISEF * ev.x;
        o.y = lo.y + bi.y + NOISEF * ev.y;
        o.z = hi.x + bi.z + NOISEF * ev.z;
        o.w = hi.y + bi.w + NOISEF * ev.w;
        *(float4*)(out + off) = o;
    }
}

// ---------------------------------------------------------------------------
// Persistent scan: 128 blocks (nt, ks), release/acquire point-to-point sync,
// HMMA split-bf16 GEMM with A (W) fragments in registers, pair-layout slabs.
// ---------------------------------------------------------------------------
__global__ void __launch_bounds__(256, 1) scan_kernel(float* __restrict__ out)
{
    extern __shared__ char smem[];
    const uint32_t sb = smem_u32(smem);
    const int tid = threadIdx.x;
    const int l = tid & 31, w = tid >> 5;
    const int nt = blockIdx.x & 15;
    const int ks = blockIdx.x >> 4;
    const int j0 = nt * 64;
    const int k0 = ks * 128;

    // Load W^T hi/lo tile [64 j][128 k] into padded smem (once)
    {
        int r = tid >> 2, c = tid & 3;
        const uint4* sh = (const uint4*)(g_wthi + (size_t)(j0 + r) * NH + k0) + c * 4;
        const uint4* sl = (const uint4*)(g_wtlo + (size_t)(j0 + r) * NH + k0) + c * 4;
        char* dh = smem + SM_WHI + r * ROWB + c * 64;
        char* dl = smem + SM_WLO + r * ROWB + c * 64;
#pragma unroll
        for (int i = 0; i < 4; i++) {
            *(uint4*)(dh + i * 16) = sh[i];
            *(uint4*)(dl + i * 16) = sl[i];
        }
    }

    // lane addresses
    const int wm = (w & 3) * 16;    // j offset of warp
    const int wn = (w >> 2) * 32;   // b offset of warp
    const uint32_t aHi = sb + SM_WHI + (wm + (l & 15)) * ROWB + (l >> 4) * 16;
    const uint32_t aLo = aHi + (SM_WLO - SM_WHI);
    const uint32_t brow = wn + ((l >> 4) << 3) + (l & 7);
    const uint32_t boff = ((l >> 3) & 1) * 16;
    const uint32_t b0Hi = sb + SM_BHI + brow * ROWB + boff;
    const uint32_t b1Hi = b0Hi + 16 * ROWB;
    const uint32_t b0Lo = b0Hi + (SM_BLO - SM_BHI);
    const uint32_t b1Lo = b1Hi + (SM_BLO - SM_BHI);

    __syncthreads();

    // Hoist A fragments (W tile) into registers: loop-invariant across t
    uint32_t Ah[8][4], Al[8][4];
#pragma unroll
    for (int kk = 0; kk < 8; kk++) {
        LDSM4(Ah[kk], aHi + kk * 32);
        LDSM4(Al[kk], aLo + kk * 32);
    }

    // slab-store coords (pair layout: part[b>>1][j][2], row stride 2048 floats)
    const int sj0 = j0 + wm + (l >> 2);
    const int sb0 = wn + 2 * (l & 3);      // even

    // epilogue coords: rows b in [8ks, 8ks+8), cols = tile nt (64 j)
    const int ej = j0 + (tid & 63);
    const int eb = 8 * ks + 2 * (tid >> 6);   // even
    const float alf = g_alpha[ej];

    // staging coords
    const int stb = tid >> 2, stc = tid & 3;
    char* dBh = smem + SM_BHI + stb * ROWB + stc * 64;
    char* dBl = smem + SM_BLO + stb * ROWB + stc * 64;

    for (int t = 0; t < TT; t++) {
        // early prefetch of pre-activations (only this block ever touches them)
        const long o0 = ((long)eb * TT + t) * NH + ej;
        const long o1 = o0 + (long)TT * NH;
        const float p0 = out[o0];
        const float p1 = out[o1];

        // point-to-point waits (3 warps poll in parallel, acquire loads)
        if (t > 0) {
            const int tgt = 8 * t;
            if (tid == 0)  { while (ldacq(&g_ecnt[2 * ks]) < tgt) __nanosleep(16); }
            if (tid == 32) { while (ldacq(&g_ecnt[2 * ks + 1]) < tgt) __nanosleep(16); }
            if (tid == 64) { while (ldacq(&g_ecnt[nt]) < tgt) __nanosleep(16); }
            __syncthreads();
        }

        // stage h slice: unpack packed hi|lo -> bf16 smem tiles
        const unsigned int* hsrc = g_hpk[t & 1];
        {
            const uint4* src = (const uint4*)(hsrc + stb * NH + k0) + stc * 8;
#pragma unroll
            for (int i = 0; i < 8; i++) {
                uint4 v = __ldcg(src + i);
                uint32_t h0 = __byte_perm(v.x, v.y, 0x7632);
                uint32_t l0 = __byte_perm(v.x, v.y, 0x5410);
                uint32_t h1 = __byte_perm(v.z, v.w, 0x7632);
                uint32_t l1 = __byte_perm(v.z, v.w, 0x5410);
                *(uint2*)(dBh + i * 8) = make_uint2(h0, h1);
                *(uint2*)(dBl + i * 8) = make_uint2(l0, l1);
            }
        }

        // prefetch step t-1 hidden state (covered by ecnt waits above)
        const float* hin32 = g_h32[t & 1];
        const float h0 = __ldcg(&hin32[eb * NH + ej]);
        const float h1 = __ldcg(&hin32[(eb + 1) * NH + ej]);

        __syncthreads();

        // GEMM: 8 k-steps of 16, split-bf16 (3 products), A in registers
        float acc[4][4];
#pragma unroll
        for (int n = 0; n < 4; n++)
#pragma unroll
            for (int i = 0; i < 4; i++) acc[n][i] = 0.0f;

#pragma unroll
        for (int kk = 0; kk < 8; kk++) {
            const uint32_t off = kk * 32;
            uint32_t bh0[4], bh1[4], bl0[4], bl1[4];
            LDSM4(bh0, b0Hi + off);
            LDSM4(bh1, b1Hi + off);
            LDSM4(bl0, b0Lo + off);
            LDSM4(bl1, b1Lo + off);
            MMA16816(acc[0], Ah[kk], bh0[0], bh0[1]);
            MMA16816(acc[1], Ah[kk], bh0[2], bh0[3]);
            MMA16816(acc[2], Ah[kk], bh1[0], bh1[1]);
            MMA16816(acc[3], Ah[kk], bh1[2], bh1[3]);
            MMA16816(acc[0], Ah[kk], bl0[0], bl0[1]);
            MMA16816(acc[1], Ah[kk], bl0[2], bl0[3]);
            MMA16816(acc[2], Ah[kk], bl1[0], bl1[1]);
            MMA16816(acc[3], Ah[kk], bl1[2], bl1[3]);
            MMA16816(acc[0], Al[kk], bh0[0], bh0[1]);
            MMA16816(acc[1], Al[kk], bh0[2], bh0[3]);
            MMA16816(acc[2], Al[kk], bh1[0], bh1[1]);
            MMA16816(acc[3], Al[kk], bh1[2], bh1[3]);
        }

        // store slab, pair layout: float2 {b, b+1} at [pair][j]
        {
            float* part = g_part[ks];
#pragma unroll
            for (int n = 0; n < 4; n++) {
                int pr = (sb0 + 8 * n) >> 1;
                *(float2*)(part + (size_t)pr * 2048 + sj0 * 2) =
                    make_float2(acc[n][0], acc[n][1]);
                *(float2*)(part + (size_t)pr * 2048 + (sj0 + 8) * 2) =
                    make_float2(acc[n][2], acc[n][3]);
            }
        }

        // release slab writes, rendezvous on tile nt's 8 slabs
        __syncthreads();
        if (tid == 0) {
            red_rel(&g_cnt[nt]);
            while (ldacq(&g_cnt[nt]) < 8 * (t + 1)) __nanosleep(16);
        }
        __syncthreads();

        // distributed epilogue: sum 8 slabs (fixed order), float2 pair loads
        {
            const size_t poff = (size_t)(eb >> 1) * 2048 + ej * 2;
            float s0 = 0.0f, s1 = 0.0f;
#pragma unroll
            for (int q = 0; q < NKS; q++) {
                float2 v = __ldcg((const float2*)(g_part[q] + poff));
                s0 += v.x; s1 += v.y;
            }
            float n0 = (1.0f - alf) * h0 + alf * ftanh(p0 + s0);
            float n1 = (1.0f - alf) * h1 + alf * ftanh(p1 + s1);
            out[o0] = n0;
            out[o1] = n1;
            float* h32o = g_h32[(t + 1) & 1];
            unsigned int* hpko = g_hpk[(t + 1) & 1];
            h32o[eb * NH + ej] = n0;
            h32o[(eb + 1) * NH + ej] = n1;
            hpko[eb * NH + ej] = packhl(n0);
            hpko[(eb + 1) * NH + ej] = packhl(n1);
        }

        // release epilogue writes for step t of tile nt
        __syncthreads();
        if (tid == 0) red_rel(&g_ecnt[nt]);
    }
}

extern "C" void kernel_launch(void* const* d_in, const int* in_sizes, int n_in,
                              void* d_out, int out_size) {
    const float* x    = (const float*)d_in[0];  // [B,T,I]
    const float* eps  = (const float*)d_in[1];  // [B,T,H]
    const float* in_w = (const float*)d_in[2];  // [H,I]
    const float* in_b = (const float*)d_in[3];  // [H]
    const float* W    = (const float*)d_in[4];  // [H,H]
    const float* taus = (const float*)d_in[5];  // [H]
    float* out = (float*)d_out;                 // [B,T,H]

    static int attr_done = 0;
    if (!attr_done) {
        cudaFuncSetAttribute(scan_kernel, cudaFuncAttributeMaxDynamicSharedMemorySize, SM_TOTAL);
        attr_done = 1;
    }

    init_kernel<<<(NB * NH + 255) / 256, 256>>>(taus);
    transpose_kernel<<<dim3(NI / 32, NH / 32), dim3(32, 8)>>>(in_w);
    wsplit_kernel<<<dim3(NH / 32, NH / 32), dim3(32, 8)>>>(W);

    dim3 pgrid(NH / 64, (NB * TT) / 64);
    proj_kernel<<<pgrid, 256>>>(x, in_b, eps, out);

    scan_kernel<<<NBLK, 256, SM_TOTAL>>>(out);
}

// round 12
// speedup vs baseline: 2.3843x; 1.0266x over previous
#include <cuda_runtime.h>
#include <cuda_bf16.h>
#include <math.h>
#include <stdint.h>

#define NB 64
#define TT 512
#define NI 256
#define NH 1024
#define NOISEF 0.1f
#define NKS 8             // k-slices of 128
#define NTILE 16          // j-tiles of 64
#define NBLK 128

// ---- static device scratch ----
__device__ float g_h32[2][NB * NH];          // fp32 hidden state [b][j], double buf
__device__ unsigned int g_hpk[2][NB * NH];   // packed bf16 hi<<16|lo of h
__device__ float g_part[NKS][NB * NH];       // split-K slabs, PAIR layout [b/2][j][2]
__device__ float g_alpha[NH];
__device__ __nv_bfloat16 g_wthi[NH * NH];    // [j][k] = bf16_hi(W[k][j])
__device__ __nv_bfloat16 g_wtlo[NH * NH];    // [j][k] = residual
__device__ __nv_bfloat16 g_xhi[NB * TT * NI];  // bf16_hi(x) [r][k]
__device__ __nv_bfloat16 g_xlo[NB * TT * NI];  // residual
__device__ __nv_bfloat16 g_iwhi[NH * NI];      // bf16_hi(in_w) [j][k]
__device__ __nv_bfloat16 g_iwlo[NH * NI];      // residual
__device__ int g_cnt[NTILE];                 // slab arrivals per tile (monotonic)
__device__ int g_ecnt[NTILE];                // epilogue parts per tile (monotonic)

// smem layout (272B-padded rows of 128 bf16 for conflict-free ldmatrix)
#define SM_WHI 0
#define SM_WLO 17408
#define SM_BHI 34816
#define SM_BLO 52224
#define SM_TOTAL 69632
#define ROWB 272

static __device__ __forceinline__ uint32_t smem_u32(const void* p) {
    uint32_t a;
    asm("{ .reg .u64 t; cvta.to.shared.u64 t, %1; cvt.u32.u64 %0, t; }" : "=r"(a) : "l"(p));
    return a;
}
// acquire poll load (gpu scope)
static __device__ __forceinline__ int ldacq(const int* p) {
    int v;
    asm volatile("ld.acquire.gpu.global.b32 %0, [%1];" : "=r"(v) : "l"(p) : "memory");
    return v;
}
// release increment (gpu scope)
static __device__ __forceinline__ void red_rel(int* p) {
    asm volatile("red.release.gpu.global.add.s32 [%0], 1;" :: "l"(p) : "memory");
}

#define LDSM4(r, a)                                                             \
    asm volatile("ldmatrix.sync.aligned.m8n8.x4.shared.b16 {%0,%1,%2,%3}, [%4];" \
        : "=r"((r)[0]), "=r"((r)[1]), "=r"((r)[2]), "=r"((r)[3]) : "r"(a))

#define MMA16816(d, a, b0, b1)                                                  \
    asm volatile("mma.sync.aligned.m16n8k16.row.col.f32.bf16.bf16.f32 "         \
        "{%0,%1,%2,%3}, {%4,%5,%6,%7}, {%8,%9}, {%0,%1,%2,%3};"                 \
        : "+f"((d)[0]), "+f"((d)[1]), "+f"((d)[2]), "+f"((d)[3])                \
        : "r"((a)[0]), "r"((a)[1]), "r"((a)[2]), "r"((a)[3]), "r"(b0), "r"(b1))

static __device__ __forceinline__ uint32_t packhl(float v) {
    __nv_bfloat16 h = __float2bfloat16(v);
    __nv_bfloat16 lo = __float2bfloat16(v - __bfloat162float(h));
    return ((uint32_t)__bfloat16_as_ushort(h) << 16) | __bfloat16_as_ushort(lo);
}
// packed bf16 pair: returns b<<16 | a (each rn-rounded)
static __device__ __forceinline__ uint32_t bf2(float a, float b) {
    uint32_t r;
    asm("cvt.rn.bf16x2.f32 %0, %1, %2;" : "=r"(r) : "f"(b), "f"(a));
    return r;
}
static __device__ __forceinline__ float bf_lo(uint32_t u) { return __uint_as_float(u << 16); }
static __device__ __forceinline__ float bf_hi(uint32_t u) { return __uint_as_float(u & 0xFFFF0000u); }
// fast tanh: exp-based, ~1e-6 abs error
static __device__ __forceinline__ float ftanh(float x) {
    float e = __expf(2.0f * x);
    return 1.0f - __fdividef(2.0f, e + 1.0f);
}

__global__ void init_kernel(const float* __restrict__ taus) {
    int idx = blockIdx.x * blockDim.x + threadIdx.x;
    if (idx < NB * NH) { g_h32[0][idx] = 0.0f; g_hpk[0][idx] = 0u; }
    if (idx < NH) {
        float s = 1.0f / (1.0f + expf(-taus[idx]));
        g_alpha[idx] = 10.0f / (s * 90.0f + 10.0f);
    }
    if (idx < NTILE) { g_cnt[idx] = 0; g_ecnt[idx] = 0; }
}

// elementwise bf16 hi/lo split: src (f32, n4*4 elems) -> dhi/dlo bf16 arrays
__global__ void split_kernel(const float* __restrict__ src, int which, int n4) {
    int idx = blockIdx.x * blockDim.x + threadIdx.x;
    if (idx >= n4) return;
    float4 v = ((const float4*)src)[idx];
    uint32_t h01 = bf2(v.x, v.y);
    uint32_t h23 = bf2(v.z, v.w);
    uint32_t l01 = bf2(v.x - bf_lo(h01), v.y - bf_hi(h01));
    uint32_t l23 = bf2(v.z - bf_lo(h23), v.w - bf_hi(h23));
    uint2* dh = which ? (uint2*)g_iwhi : (uint2*)g_xhi;
    uint2* dl = which ? (uint2*)g_iwlo : (uint2*)g_xlo;
    dh[idx] = make_uint2(h01, h23);
    dl[idx] = make_uint2(l01, l23);
}

// W [k][j] -> g_wthi/g_wtlo [j][k] bf16 split
__global__ void wsplit_kernel(const float* __restrict__ W) {
    __shared__ float t[32][33];
    int bk = blockIdx.x * 32;
    int bj = blockIdx.y * 32;
    int tx = threadIdx.x, ty = threadIdx.y;
    for (int i = ty; i < 32; i += 8) t[i][tx] = W[(bk + i) * NH + bj + tx];
    __syncthreads();
    for (int i = ty; i < 32; i += 8) {
        float v = t[tx][i];
        __nv_bfloat16 hi = __float2bfloat16(v);
        float r = v - __bfloat162float(hi);
        g_wthi[(bj + i) * NH + bk + tx] = hi;
        g_wtlo[(bj + i) * NH + bk + tx] = __float2bfloat16(r);
    }
}

// ---------------------------------------------------------------------------
// Input projection via HMMA split-bf16:
// out[r][j] = x[r]·in_w[j] + bias[j] + NOISE*eps[r][j]
// 64r x 64j tile per block; K=256 in two k=128 chunks; scan-verified mapping.
// ---------------------------------------------------------------------------
__global__ void __launch_bounds__(256) proj_kernel(
    const float* __restrict__ bias, const float* __restrict__ eps,
    float* __restrict__ out)
{
    extern __shared__ char smem[];
    const uint32_t sb = smem_u32(smem);
    const int tid = threadIdx.x;
    const int l = tid & 31, w = tid >> 5;
    const int j0 = blockIdx.x * 64;
    const int r0 = blockIdx.y * 64;
    const int wm = (w & 3) * 16;    // r offset of warp
    const int wn = (w >> 2) * 32;   // j offset of warp

    // lane addresses (identical mapping to scan GEMM)
    const uint32_t aHi = sb + SM_WHI + (wm + (l & 15)) * ROWB + (l >> 4) * 16;
    const uint32_t aLo = aHi + (SM_WLO - SM_WHI);
    const uint32_t brow = wn + ((l >> 4) << 3) + (l & 7);
    const uint32_t boff = ((l >> 3) & 1) * 16;
    const uint32_t b0Hi = sb + SM_BHI + brow * ROWB + boff;
    const uint32_t b1Hi = b0Hi + 16 * ROWB;
    const uint32_t b0Lo = b0Hi + (SM_BLO - SM_BHI);
    const uint32_t b1Lo = b1Hi + (SM_BLO - SM_BHI);

    const int str = tid >> 2, stc = tid & 3;   // staging: 4 threads per 64-row

    float acc[4][4];
#pragma unroll
    for (int n = 0; n < 4; n++)
#pragma unroll
        for (int i = 0; i < 4; i++) acc[n][i] = 0.0f;

#pragma unroll
    for (int kc = 0; kc < 2; kc++) {
        const int kb = kc * 128;
        if (kc) __syncthreads();   // protect prior chunk's smem reads
        // stage x tile (A: rows r0..r0+63) and w tile (B: rows j0..j0+63)
        const char* sxh = (const char*)(g_xhi + (size_t)(r0 + str) * NI + kb) + stc * 64;
        const char* sxl = (const char*)(g_xlo + (size_t)(r0 + str) * NI + kb) + stc * 64;
        const char* swh = (const char*)(g_iwhi + (size_t)(j0 + str) * NI + kb) + stc * 64;
        const char* swl = (const char*)(g_iwlo + (size_t)(j0 + str) * NI + kb) + stc * 64;
        char* dxh = smem + SM_WHI + str * ROWB + stc * 64;
        char* dxl = smem + SM_WLO + str * ROWB + stc * 64;
        char* dwh = smem + SM_BHI + str * ROWB + stc * 64;
        char* dwl = smem + SM_BLO + str * ROWB + stc * 64;
#pragma unroll
        for (int i = 0; i < 4; i++) {
            *(uint4*)(dxh + i * 16) = *(const uint4*)(sxh + i * 16);
            *(uint4*)(dxl + i * 16) = *(const uint4*)(sxl + i * 16);
            *(uint4*)(dwh + i * 16) = *(const uint4*)(swh + i * 16);
            *(uint4*)(dwl + i * 16) = *(const uint4*)(swl + i * 16);
        }
        __syncthreads();

#pragma unroll
        for (int kk = 0; kk < 8; kk++) {
            const uint32_t off = kk * 32;
            uint32_t ah[4], al4[4], bh0[4], bh1[4], bl0[4], bl1[4];
            LDSM4(ah, aHi + off);
            LDSM4(al4, aLo + off);
            LDSM4(bh0, b0Hi + off);
            LDSM4(bh1, b1Hi + off);
            LDSM4(bl0, b0Lo + off);
            LDSM4(bl1, b1Lo + off);
            MMA16816(acc[0], ah, bh0[0], bh0[1]);
            MMA16816(acc[1], ah, bh0[2], bh0[3]);
            MMA16816(acc[2], ah, bh1[0], bh1[1]);
            MMA16816(acc[3], ah, bh1[2], bh1[3]);
            MMA16816(acc[0], ah, bl0[0], bl0[1]);
            MMA16816(acc[1], ah, bl0[2], bl0[3]);
            MMA16816(acc[2], ah, bl1[0], bl1[1]);
            MMA16816(acc[3], ah, bl1[2], bl1[3]);
            MMA16816(acc[0], al4, bh0[0], bh0[1]);
            MMA16816(acc[1], al4, bh0[2], bh0[3]);
            MMA16816(acc[2], al4, bh1[0], bh1[1]);
            MMA16816(acc[3], al4, bh1[2], bh1[3]);
        }
    }

    // epilogue: D[r][j]; rows er, er+8; col pairs ejc + 8n
    const int er = r0 + wm + (l >> 2);
    const int ejc = j0 + wn + 2 * (l & 3);
#pragma unroll
    for (int n = 0; n < 4; n++) {
        int j = ejc + 8 * n;
        float2 bi = *(const float2*)(bias + j);
        long off0 = (long)er * NH + j;
        float2 ev0 = *(const float2*)(eps + off0);
        *(float2*)(out + off0) = make_float2(acc[n][0] + bi.x + NOISEF * ev0.x,
                                             acc[n][1] + bi.y + NOISEF * ev0.y);
        long off1 = (long)(er + 8) * NH + j;
        float2 ev1 = *(const float2*)(eps + off1);
        *(float2*)(out + off1) = make_float2(acc[n][2] + bi.x + NOISEF * ev1.x,
                                             acc[n][3] + bi.y + NOISEF * ev1.y);
    }
}

// ---------------------------------------------------------------------------
// Persistent scan (unchanged from R11): 128 blocks (nt, ks), release/acquire
// point-to-point sync, HMMA split-bf16 GEMM, A fragments in registers.
// ---------------------------------------------------------------------------
__global__ void __launch_bounds__(256, 1) scan_kernel(float* __restrict__ out)
{
    extern __shared__ char smem[];
    const uint32_t sb = smem_u32(smem);
    const int tid = threadIdx.x;
    const int l = tid & 31, w = tid >> 5;
    const int nt = blockIdx.x & 15;
    const int ks = blockIdx.x >> 4;
    const int j0 = nt * 64;
    const int k0 = ks * 128;

    // Load W^T hi/lo tile [64 j][128 k] into padded smem (once)
    {
        int r = tid >> 2, c = tid & 3;
        const uint4* sh = (const uint4*)(g_wthi + (size_t)(j0 + r) * NH + k0) + c * 4;
        const uint4* sl = (const uint4*)(g_wtlo + (size_t)(j0 + r) * NH + k0) + c * 4;
        char* dh = smem + SM_WHI + r * ROWB + c * 64;
        char* dl = smem + SM_WLO + r * ROWB + c * 64;
#pragma unroll
        for (int i = 0; i < 4; i++) {
            *(uint4*)(dh + i * 16) = sh[i];
            *(uint4*)(dl + i * 16) = sl[i];
        }
    }

    // lane addresses
    const int wm = (w & 3) * 16;
    const int wn = (w >> 2) * 32;
    const uint32_t aHi = sb + SM_WHI + (wm + (l & 15)) * ROWB + (l >> 4) * 16;
    const uint32_t aLo = aHi + (SM_WLO - SM_WHI);
    const uint32_t brow = wn + ((l >> 4) << 3) + (l & 7);
    const uint32_t boff = ((l >> 3) & 1) * 16;
    const uint32_t b0Hi = sb + SM_BHI + brow * ROWB + boff;
    const uint32_t b1Hi = b0Hi + 16 * ROWB;
    const uint32_t b0Lo = b0Hi + (SM_BLO - SM_BHI);
    const uint32_t b1Lo = b1Hi + (SM_BLO - SM_BHI);

    __syncthreads();

    // Hoist A fragments (W tile) into registers
    uint32_t Ah[8][4], Al[8][4];
#pragma unroll
    for (int kk = 0; kk < 8; kk++) {
        LDSM4(Ah[kk], aHi + kk * 32);
        LDSM4(Al[kk], aLo + kk * 32);
    }

    // slab-store coords (pair layout)
    const int sj0 = j0 + wm + (l >> 2);
    const int sb0 = wn + 2 * (l & 3);

    // epilogue coords
    const int ej = j0 + (tid & 63);
    const int eb = 8 * ks + 2 * (tid >> 6);
    const float alf = g_alpha[ej];

    // staging coords
    const int stb = tid >> 2, stc = tid & 3;
    char* dBh = smem + SM_BHI + stb * ROWB + stc * 64;
    char* dBl = smem + SM_BLO + stb * ROWB + stc * 64;

    for (int t = 0; t < TT; t++) {
        const long o0 = ((long)eb * TT + t) * NH + ej;
        const long o1 = o0 + (long)TT * NH;
        const float p0 = out[o0];
        const float p1 = out[o1];

        if (t > 0) {
            const int tgt = 8 * t;
            if (tid == 0)  { while (ldacq(&g_ecnt[2 * ks]) < tgt) __nanosleep(16); }
            if (tid == 32) { while (ldacq(&g_ecnt[2 * ks + 1]) < tgt) __nanosleep(16); }
            if (tid == 64) { while (ldacq(&g_ecnt[nt]) < tgt) __nanosleep(16); }
            __syncthreads();
        }

        const unsigned int* hsrc = g_hpk[t & 1];
        {
            const uint4* src = (const uint4*)(hsrc + stb * NH + k0) + stc * 8;
#pragma unroll
            for (int i = 0; i < 8; i++) {
                uint4 v = __ldcg(src + i);
                uint32_t h0 = __byte_perm(v.x, v.y, 0x7632);
                uint32_t l0 = __byte_perm(v.x, v.y, 0x5410);
                uint32_t h1 = __byte_perm(v.z, v.w, 0x7632);
                uint32_t l1 = __byte_perm(v.z, v.w, 0x5410);
                *(uint2*)(dBh + i * 8) = make_uint2(h0, h1);
                *(uint2*)(dBl + i * 8) = make_uint2(l0, l1);
            }
        }

        const float* hin32 = g_h32[t & 1];
        const float h0 = __ldcg(&hin32[eb * NH + ej]);
        const float h1 = __ldcg(&hin32[(eb + 1) * NH + ej]);

        __syncthreads();

        float acc[4][4];
#pragma unroll
        for (int n = 0; n < 4; n++)
#pragma unroll
            for (int i = 0; i < 4; i++) acc[n][i] = 0.0f;

#pragma unroll
        for (int kk = 0; kk < 8; kk++) {
            const uint32_t off = kk * 32;
            uint32_t bh0[4], bh1[4], bl0[4], bl1[4];
            LDSM4(bh0, b0Hi + off);
            LDSM4(bh1, b1Hi + off);
            LDSM4(bl0, b0Lo + off);
            LDSM4(bl1, b1Lo + off);
            MMA16816(acc[0], Ah[kk], bh0[0], bh0[1]);
            MMA16816(acc[1], Ah[kk], bh0[2], bh0[3]);
            MMA16816(acc[2], Ah[kk], bh1[0], bh1[1]);
            MMA16816(acc[3], Ah[kk], bh1[2], bh1[3]);
            MMA16816(acc[0], Ah[kk], bl0[0], bl0[1]);
            MMA16816(acc[1], Ah[kk], bl0[2], bl0[3]);
            MMA16816(acc[2], Ah[kk], bl1[0], bl1[1]);
            MMA16816(acc[3], Ah[kk], bl1[2], bl1[3]);
            MMA16816(acc[0], Al[kk], bh0[0], bh0[1]);
            MMA16816(acc[1], Al[kk], bh0[2], bh0[3]);
            MMA16816(acc[2], Al[kk], bh1[0], bh1[1]);
            MMA16816(acc[3], Al[kk], bh1[2], bh1[3]);
        }

        {
            float* part = g_part[ks];
#pragma unroll
            for (int n = 0; n < 4; n++) {
                int pr = (sb0 + 8 * n) >> 1;
                *(float2*)(part + (size_t)pr * 2048 + sj0 * 2) =
                    make_float2(acc[n][0], acc[n][1]);
                *(float2*)(part + (size_t)pr * 2048 + (sj0 + 8) * 2) =
                    make_float2(acc[n][2], acc[n][3]);
            }
        }

        __syncthreads();
        if (tid == 0) {
            red_rel(&g_cnt[nt]);
            while (ldacq(&g_cnt[nt]) < 8 * (t + 1)) __nanosleep(16);
        }
        __syncthreads();

        {
            const size_t poff = (size_t)(eb >> 1) * 2048 + ej * 2;
            float s0 = 0.0f, s1 = 0.0f;
#pragma unroll
            for (int q = 0; q < NKS; q++) {
                float2 v = __ldcg((const float2*)(g_part[q] + poff));
                s0 += v.x; s1 += v.y;
            }
            float n0 = (1.0f - alf) * h0 + alf * ftanh(p0 + s0);
            float n1 = (1.0f - alf) * h1 + alf * ftanh(p1 + s1);
            out[o0] = n0;
            out[o1] = n1;
            float* h32o = g_h32[(t + 1) & 1];
            unsigned int* hpko = g_hpk[(t + 1) & 1];
            h32o[eb * NH + ej] = n0;
            h32o[(eb + 1) * NH + ej] = n1;
            hpko[eb * NH + ej] = packhl(n0);
            hpko[(eb + 1) * NH + ej] = packhl(n1);
        }

        __syncthreads();
        if (tid == 0) red_rel(&g_ecnt[nt]);
    }
}

extern "C" void kernel_launch(void* const* d_in, const int* in_sizes, int n_in,
                              void* d_out, int out_size) {
    const float* x    = (const float*)d_in[0];  // [B,T,I]
    const float* eps  = (const float*)d_in[1];  // [B,T,H]
    const float* in_w = (const float*)d_in[2];  // [H,I]
    const float* in_b = (const float*)d_in[3];  // [H]
    const float* W    = (const float*)d_in[4];  // [H,H]
    const float* taus = (const float*)d_in[5];  // [H]
    float* out = (float*)d_out;                 // [B,T,H]

    static int attr_done = 0;
    if (!attr_done) {
        cudaFuncSetAttribute(scan_kernel, cudaFuncAttributeMaxDynamicSharedMemorySize, SM_TOTAL);
        cudaFuncSetAttribute(proj_kernel, cudaFuncAttributeMaxDynamicSharedMemorySize, SM_TOTAL);
        attr_done = 1;
    }

    init_kernel<<<(NB * NH + 255) / 256, 256>>>(taus);
    wsplit_kernel<<<dim3(NH / 32, NH / 32), dim3(32, 8)>>>(W);
    split_kernel<<<(NB * TT * NI / 4 + 255) / 256, 256>>>(x, 0, NB * TT * NI / 4);
    split_kernel<<<(NH * NI / 4 + 255) / 256, 256>>>(in_w, 1, NH * NI / 4);

    dim3 pgrid(NH / 64, (NB * TT) / 64);   // (16, 512)
    proj_kernel<<<pgrid, 256, SM_TOTAL>>>(in_b, eps, out);

    scan_kernel<<<NBLK, 256, SM_TOTAL>>>(out);
}

// round 13
// speedup vs baseline: 2.7384x; 1.1485x over previous
#include <cuda_runtime.h>
#include <cuda_bf16.h>
#include <math.h>
#include <stdint.h>

#define NB 64
#define TT 512
#define NI 256
#define NH 1024
#define NOISEF 0.1f
#define NKS 8             // k-slices of 128
#define NTILE 16          // j-tiles of 64
#define NBLK 128

// ---- static device scratch ----
__device__ float g_h32[2][NB * NH];            // fp32 hidden state, double buf
__device__ __nv_bfloat16 g_hh[2][NB * NH];     // bf16 hi of h (planar)
__device__ __nv_bfloat16 g_hl[2][NB * NH];     // bf16 lo residual (planar)
__device__ float g_part[NKS][NB * NH];         // split-K slabs, PAIR layout [b/2][j][2]
__device__ float g_alpha[NH];
__device__ __nv_bfloat16 g_wthi[NH * NH];      // [j][k] = bf16_hi(W[k][j])
__device__ __nv_bfloat16 g_wtlo[NH * NH];      // [j][k] = residual
__device__ __nv_bfloat16 g_xhi[NB * TT * NI];  // bf16_hi(x) [r][k]
__device__ __nv_bfloat16 g_xlo[NB * TT * NI];
__device__ __nv_bfloat16 g_iwhi[NH * NI];      // bf16_hi(in_w) [j][k]
__device__ __nv_bfloat16 g_iwlo[NH * NI];
__device__ int g_cnt[NTILE];                   // slab arrivals per tile (monotonic)
__device__ int g_ecnt[NTILE];                  // epilogue parts per tile (monotonic)

// smem layout (272B-padded rows of 128 bf16 for conflict-free ldmatrix)
#define SM_WHI 0
#define SM_WLO 17408
#define SM_BHI 34816
#define SM_BLO 52224
#define SM_TOTAL 69632
#define ROWB 272

static __device__ __forceinline__ uint32_t smem_u32(const void* p) {
    uint32_t a;
    asm("{ .reg .u64 t; cvta.to.shared.u64 t, %1; cvt.u32.u64 %0, t; }" : "=r"(a) : "l"(p));
    return a;
}
static __device__ __forceinline__ int ldacq(const int* p) {
    int v;
    asm volatile("ld.acquire.gpu.global.b32 %0, [%1];" : "=r"(v) : "l"(p) : "memory");
    return v;
}
static __device__ __forceinline__ void red_rel(int* p) {
    asm volatile("red.release.gpu.global.add.s32 [%0], 1;" :: "l"(p) : "memory");
}

#define LDSM4(r, a)                                                             \
    asm volatile("ldmatrix.sync.aligned.m8n8.x4.shared.b16 {%0,%1,%2,%3}, [%4];" \
        : "=r"((r)[0]), "=r"((r)[1]), "=r"((r)[2]), "=r"((r)[3]) : "r"(a))

#define MMA16816(d, a, b0, b1)                                                  \
    asm volatile("mma.sync.aligned.m16n8k16.row.col.f32.bf16.bf16.f32 "         \
        "{%0,%1,%2,%3}, {%4,%5,%6,%7}, {%8,%9}, {%0,%1,%2,%3};"                 \
        : "+f"((d)[0]), "+f"((d)[1]), "+f"((d)[2]), "+f"((d)[3])                \
        : "r"((a)[0]), "r"((a)[1]), "r"((a)[2]), "r"((a)[3]), "r"(b0), "r"(b1))

static __device__ __forceinline__ uint32_t bf2(float a, float b) {
    uint32_t r;
    asm("cvt.rn.bf16x2.f32 %0, %1, %2;" : "=r"(r) : "f"(b), "f"(a));
    return r;
}
static __device__ __forceinline__ float bf_lo(uint32_t u) { return __uint_as_float(u << 16); }
static __device__ __forceinline__ float bf_hi(uint32_t u) { return __uint_as_float(u & 0xFFFF0000u); }
static __device__ __forceinline__ float ftanh(float x) {
    float e = __expf(2.0f * x);
    return 1.0f - __fdividef(2.0f, e + 1.0f);
}

__global__ void init_kernel(const float* __restrict__ taus) {
    int idx = blockIdx.x * blockDim.x + threadIdx.x;
    if (idx < NB * NH) {
        g_h32[0][idx] = 0.0f;
        g_hh[0][idx] = __float2bfloat16(0.0f);
        g_hl[0][idx] = __float2bfloat16(0.0f);
    }
    if (idx < NH) {
        float s = 1.0f / (1.0f + expf(-taus[idx]));
        g_alpha[idx] = 10.0f / (s * 90.0f + 10.0f);
    }
    if (idx < NTILE) { g_cnt[idx] = 0; g_ecnt[idx] = 0; }
}

// elementwise bf16 hi/lo split for proj inputs
__global__ void split_kernel(const float* __restrict__ src, int which, int n4) {
    int idx = blockIdx.x * blockDim.x + threadIdx.x;
    if (idx >= n4) return;
    float4 v = ((const float4*)src)[idx];
    uint32_t h01 = bf2(v.x, v.y);
    uint32_t h23 = bf2(v.z, v.w);
    uint32_t l01 = bf2(v.x - bf_lo(h01), v.y - bf_hi(h01));
    uint32_t l23 = bf2(v.z - bf_lo(h23), v.w - bf_hi(h23));
    uint2* dh = which ? (uint2*)g_iwhi : (uint2*)g_xhi;
    uint2* dl = which ? (uint2*)g_iwlo : (uint2*)g_xlo;
    dh[idx] = make_uint2(h01, h23);
    dl[idx] = make_uint2(l01, l23);
}

// W [k][j] -> g_wthi/g_wtlo [j][k] bf16 split
__global__ void wsplit_kernel(const float* __restrict__ W) {
    __shared__ float t[32][33];
    int bk = blockIdx.x * 32;
    int bj = blockIdx.y * 32;
    int tx = threadIdx.x, ty = threadIdx.y;
    for (int i = ty; i < 32; i += 8) t[i][tx] = W[(bk + i) * NH + bj + tx];
    __syncthreads();
    for (int i = ty; i < 32; i += 8) {
        float v = t[tx][i];
        __nv_bfloat16 hi = __float2bfloat16(v);
        float r = v - __bfloat162float(hi);
        g_wthi[(bj + i) * NH + bk + tx] = hi;
        g_wtlo[(bj + i) * NH + bk + tx] = __float2bfloat16(r);
    }
}

// ---------------------------------------------------------------------------
// Input projection via HMMA split-bf16 (unchanged from R12)
// ---------------------------------------------------------------------------
__global__ void __launch_bounds__(256) proj_kernel(
    const float* __restrict__ bias, const float* __restrict__ eps,
    float* __restrict__ out)
{
    extern __shared__ char smem[];
    const uint32_t sb = smem_u32(smem);
    const int tid = threadIdx.x;
    const int l = tid & 31, w = tid >> 5;
    const int j0 = blockIdx.x * 64;
    const int r0 = blockIdx.y * 64;
    const int wm = (w & 3) * 16;
    const int wn = (w >> 2) * 32;

    const uint32_t aHi = sb + SM_WHI + (wm + (l & 15)) * ROWB + (l >> 4) * 16;
    const uint32_t aLo = aHi + (SM_WLO - SM_WHI);
    const uint32_t brow = wn + ((l >> 4) << 3) + (l & 7);
    const uint32_t boff = ((l >> 3) & 1) * 16;
    const uint32_t b0Hi = sb + SM_BHI + brow * ROWB + boff;
    const uint32_t b1Hi = b0Hi + 16 * ROWB;
    const uint32_t b0Lo = b0Hi + (SM_BLO - SM_BHI);
    const uint32_t b1Lo = b1Hi + (SM_BLO - SM_BHI);

    const int str = tid >> 2, stc = tid & 3;

    float acc[4][4];
#pragma unroll
    for (int n = 0; n < 4; n++)
#pragma unroll
        for (int i = 0; i < 4; i++) acc[n][i] = 0.0f;

#pragma unroll
    for (int kc = 0; kc < 2; kc++) {
        const int kb = kc * 128;
        if (kc) __syncthreads();
        const char* sxh = (const char*)(g_xhi + (size_t)(r0 + str) * NI + kb) + stc * 64;
        const char* sxl = (const char*)(g_xlo + (size_t)(r0 + str) * NI + kb) + stc * 64;
        const char* swh = (const char*)(g_iwhi + (size_t)(j0 + str) * NI + kb) + stc * 64;
        const char* swl = (const char*)(g_iwlo + (size_t)(j0 + str) * NI + kb) + stc * 64;
        char* dxh = smem + SM_WHI + str * ROWB + stc * 64;
        char* dxl = smem + SM_WLO + str * ROWB + stc * 64;
        char* dwh = smem + SM_BHI + str * ROWB + stc * 64;
        char* dwl = smem + SM_BLO + str * ROWB + stc * 64;
#pragma unroll
        for (int i = 0; i < 4; i++) {
            *(uint4*)(dxh + i * 16) = *(const uint4*)(sxh + i * 16);
            *(uint4*)(dxl + i * 16) = *(const uint4*)(sxl + i * 16);
            *(uint4*)(dwh + i * 16) = *(const uint4*)(swh + i * 16);
            *(uint4*)(dwl + i * 16) = *(const uint4*)(swl + i * 16);
        }
        __syncthreads();

#pragma unroll
        for (int kk = 0; kk < 8; kk++) {
            const uint32_t off = kk * 32;
            uint32_t ah[4], al4[4], bh0[4], bh1[4], bl0[4], bl1[4];
            LDSM4(ah, aHi + off);
            LDSM4(al4, aLo + off);
            LDSM4(bh0, b0Hi + off);
            LDSM4(bh1, b1Hi + off);
            LDSM4(bl0, b0Lo + off);
            LDSM4(bl1, b1Lo + off);
            MMA16816(acc[0], ah, bh0[0], bh0[1]);
            MMA16816(acc[1], ah, bh0[2], bh0[3]);
            MMA16816(acc[2], ah, bh1[0], bh1[1]);
            MMA16816(acc[3], ah, bh1[2], bh1[3]);
            MMA16816(acc[0], ah, bl0[0], bl0[1]);
            MMA16816(acc[1], ah, bl0[2], bl0[3]);
            MMA16816(acc[2], ah, bl1[0], bl1[1]);
            MMA16816(acc[3], ah, bl1[2], bl1[3]);
            MMA16816(acc[0], al4, bh0[0], bh0[1]);
            MMA16816(acc[1], al4, bh0[2], bh0[3]);
            MMA16816(acc[2], al4, bh1[0], bh1[1]);
            MMA16816(acc[3], al4, bh1[2], bh1[3]);
        }
    }

    const int er = r0 + wm + (l >> 2);
    const int ejc = j0 + wn + 2 * (l & 3);
#pragma unroll
    for (int n = 0; n < 4; n++) {
        int j = ejc + 8 * n;
        float2 bi = *(const float2*)(bias + j);
        long off0 = (long)er * NH + j;
        float2 ev0 = *(const float2*)(eps + off0);
        *(float2*)(out + off0) = make_float2(acc[n][0] + bi.x + NOISEF * ev0.x,
                                             acc[n][1] + bi.y + NOISEF * ev0.y);
        long off1 = (long)(er + 8) * NH + j;
        float2 ev1 = *(const float2*)(eps + off1);
        *(float2*)(out + off1) = make_float2(acc[n][2] + bi.x + NOISEF * ev1.x,
                                             acc[n][3] + bi.y + NOISEF * ev1.y);
    }
}

// ---------------------------------------------------------------------------
// Persistent scan: 128 blocks x 512 threads (16 warps, 4/SMSP).
// Point-to-point release/acquire sync (R11 protocol, tid<256 epilogue).
// Planar bf16 hi/lo h arrays: stage = pure LDG->STS, no byte-permutes.
// ---------------------------------------------------------------------------
__global__ void __launch_bounds__(512, 1) scan_kernel(float* __restrict__ out)
{
    extern __shared__ char smem[];
    const uint32_t sb = smem_u32(smem);
    const int tid = threadIdx.x;
    const int l = tid & 31, w = tid >> 5;
    const int nt = blockIdx.x & 15;
    const int ks = blockIdx.x >> 4;
    const int j0 = nt * 64;
    const int k0 = ks * 128;

    // Load W^T hi/lo tile [64 j][128 k] into padded smem (once)
    for (int idx = tid; idx < 512; idx += 512) {
        int r = idx >> 3, c = idx & 7;
        *(uint4*)(smem + SM_WHI + r * ROWB + c * 32) =
            *(const uint4*)((const char*)(g_wthi + (size_t)(j0 + r) * NH + k0) + c * 32);
        *(uint4*)(smem + SM_WHI + r * ROWB + c * 32 + 16) =
            *(const uint4*)((const char*)(g_wthi + (size_t)(j0 + r) * NH + k0) + c * 32 + 16);
        *(uint4*)(smem + SM_WLO + r * ROWB + c * 32) =
            *(const uint4*)((const char*)(g_wtlo + (size_t)(j0 + r) * NH + k0) + c * 32);
        *(uint4*)(smem + SM_WLO + r * ROWB + c * 32 + 16) =
            *(const uint4*)((const char*)(g_wtlo + (size_t)(j0 + r) * NH + k0) + c * 32 + 16);
    }

    // 16-warp partition: warp covers 16 j x 16 b
    const int wm = (w & 3) * 16;    // j offset
    const int wn = (w >> 2) * 16;   // b offset
    const uint32_t aHi = sb + SM_WHI + (wm + (l & 15)) * ROWB + (l >> 4) * 16;
    const uint32_t aLo = aHi + (SM_WLO - SM_WHI);
    const uint32_t brow = wn + ((l >> 4) << 3) + (l & 7);
    const uint32_t boff = ((l >> 3) & 1) * 16;
    const uint32_t b0Hi = sb + SM_BHI + brow * ROWB + boff;
    const uint32_t b0Lo = b0Hi + (SM_BLO - SM_BHI);

    __syncthreads();

    // Hoist A fragments (W tile) into registers
    uint32_t Ah[8][4], Al[8][4];
#pragma unroll
    for (int kk = 0; kk < 8; kk++) {
        LDSM4(Ah[kk], aHi + kk * 32);
        LDSM4(Al[kk], aLo + kk * 32);
    }

    // slab-store coords (pair layout [b/2][j][2])
    const int sj0 = j0 + wm + (l >> 2);
    const int sb0 = wn + 2 * (l & 3);

    // epilogue coords (tid < 256 only): rows 8ks..8ks+8, 64 j of tile nt
    const bool epi = tid < 256;
    const int ej = j0 + (tid & 63);
    const int eb = 8 * ks + 2 * ((tid & 255) >> 6);
    const float alf = epi ? g_alpha[ej] : 0.0f;

    // staging coords: 512 threads, each 16 k-values of one b-row (hi+lo)
    const int stb = tid >> 3, stc = tid & 7;
    char* dBh = smem + SM_BHI + stb * ROWB + stc * 32;
    char* dBl = smem + SM_BLO + stb * ROWB + stc * 32;

    for (int t = 0; t < TT; t++) {
        // early prefetch of pre-activations (only this block touches them)
        const long o0 = ((long)eb * TT + t) * NH + ej;
        const long o1 = o0 + (long)TT * NH;
        float p0 = 0.0f, p1 = 0.0f;
        if (epi) { p0 = out[o0]; p1 = out[o1]; }

        // point-to-point waits (3 warps poll in parallel, acquire loads)
        if (t > 0) {
            const int tgt = 8 * t;
            if (tid == 0)  { while (ldacq(&g_ecnt[2 * ks]) < tgt) __nanosleep(16); }
            if (tid == 32) { while (ldacq(&g_ecnt[2 * ks + 1]) < tgt) __nanosleep(16); }
            if (tid == 64) { while (ldacq(&g_ecnt[nt]) < tgt) __nanosleep(16); }
            __syncthreads();
        }

        // stage h slice: planar hi/lo, pure LDG.128 -> STS.128
        {
            const char* sh = (const char*)(g_hh[t & 1] + stb * NH + k0) + stc * 32;
            const char* sl = (const char*)(g_hl[t & 1] + stb * NH + k0) + stc * 32;
            uint4 v0 = __ldcg((const uint4*)sh);
            uint4 v1 = __ldcg((const uint4*)(sh + 16));
            uint4 v2 = __ldcg((const uint4*)sl);
            uint4 v3 = __ldcg((const uint4*)(sl + 16));
            *(uint4*)dBh = v0;
            *(uint4*)(dBh + 16) = v1;
            *(uint4*)dBl = v2;
            *(uint4*)(dBl + 16) = v3;
        }

        // prefetch step t-1 hidden state (covered by ecnt waits)
        float h0 = 0.0f, h1 = 0.0f;
        if (epi) {
            const float* hin32 = g_h32[t & 1];
            h0 = __ldcg(&hin32[eb * NH + ej]);
            h1 = __ldcg(&hin32[(eb + 1) * NH + ej]);
        }

        __syncthreads();

        // GEMM: 8 k-steps of 16, split-bf16 (3 products), A in registers
        float acc[2][4];
#pragma unroll
        for (int n = 0; n < 2; n++)
#pragma unroll
            for (int i = 0; i < 4; i++) acc[n][i] = 0.0f;

#pragma unroll
        for (int kk = 0; kk < 8; kk++) {
            const uint32_t off = kk * 32;
            uint32_t bh0[4], bl0[4];
            LDSM4(bh0, b0Hi + off);
            LDSM4(bl0, b0Lo + off);
            MMA16816(acc[0], Ah[kk], bh0[0], bh0[1]);
            MMA16816(acc[1], Ah[kk], bh0[2], bh0[3]);
            MMA16816(acc[0], Ah[kk], bl0[0], bl0[1]);
            MMA16816(acc[1], Ah[kk], bl0[2], bl0[3]);
            MMA16816(acc[0], Al[kk], bh0[0], bh0[1]);
            MMA16816(acc[1], Al[kk], bh0[2], bh0[3]);
        }

        // store slab, pair layout
        {
            float* part = g_part[ks];
#pragma unroll
            for (int n = 0; n < 2; n++) {
                int pr = (sb0 + 8 * n) >> 1;
                *(float2*)(part + (size_t)pr * 2048 + sj0 * 2) =
                    make_float2(acc[n][0], acc[n][1]);
                *(float2*)(part + (size_t)pr * 2048 + (sj0 + 8) * 2) =
                    make_float2(acc[n][2], acc[n][3]);
            }
        }

        // release slab writes, rendezvous on tile nt's 8 slabs
        __syncthreads();
        if (tid == 0) {
            red_rel(&g_cnt[nt]);
            while (ldacq(&g_cnt[nt]) < 8 * (t + 1)) __nanosleep(16);
        }
        __syncthreads();

        // distributed epilogue (tid < 256)
        if (epi) {
            const size_t poff = (size_t)(eb >> 1) * 2048 + ej * 2;
            float s0 = 0.0f, s1 = 0.0f;
#pragma unroll
            for (int q = 0; q < NKS; q++) {
                float2 v = __ldcg((const float2*)(g_part[q] + poff));
                s0 += v.x; s1 += v.y;
            }
            float n0 = (1.0f - alf) * h0 + alf * ftanh(p0 + s0);
            float n1 = (1.0f - alf) * h1 + alf * ftanh(p1 + s1);
            out[o0] = n0;
            out[o1] = n1;
            float* h32o = g_h32[(t + 1) & 1];
            __nv_bfloat16* hho = g_hh[(t + 1) & 1];
            __nv_bfloat16* hlo = g_hl[(t + 1) & 1];
            h32o[eb * NH + ej] = n0;
            h32o[(eb + 1) * NH + ej] = n1;
            __nv_bfloat16 b0 = __float2bfloat16(n0);
            __nv_bfloat16 b1 = __float2bfloat16(n1);
            hho[eb * NH + ej] = b0;
            hho[(eb + 1) * NH + ej] = b1;
            hlo[eb * NH + ej] = __float2bfloat16(n0 - __bfloat162float(b0));
            hlo[(eb + 1) * NH + ej] = __float2bfloat16(n1 - __bfloat162float(b1));
        }

        // release epilogue writes for step t of tile nt
        __syncthreads();
        if (tid == 0) red_rel(&g_ecnt[nt]);
    }
}

extern "C" void kernel_launch(void* const* d_in, const int* in_sizes, int n_in,
                              void* d_out, int out_size) {
    const float* x    = (const float*)d_in[0];  // [B,T,I]
    const float* eps  = (const float*)d_in[1];  // [B,T,H]
    const float* in_w = (const float*)d_in[2];  // [H,I]
    const float* in_b = (const float*)d_in[3];  // [H]
    const float* W    = (const float*)d_in[4];  // [H,H]
    const float* taus = (const float*)d_in[5];  // [H]
    float* out = (float*)d_out;                 // [B,T,H]

    static int attr_done = 0;
    if (!attr_done) {
        cudaFuncSetAttribute(scan_kernel, cudaFuncAttributeMaxDynamicSharedMemorySize, SM_TOTAL);
        cudaFuncSetAttribute(proj_kernel, cudaFuncAttributeMaxDynamicSharedMemorySize, SM_TOTAL);
        attr_done = 1;
    }

    init_kernel<<<(NB * NH + 255) / 256, 256>>>(taus);
    wsplit_kernel<<<dim3(NH / 32, NH / 32), dim3(32, 8)>>>(W);
    split_kernel<<<(NB * TT * NI / 4 + 255) / 256, 256>>>(x, 0, NB * TT * NI / 4);
    split_kernel<<<(NH * NI / 4 + 255) / 256, 256>>>(in_w, 1, NH * NI / 4);

    dim3 pgrid(NH / 64, (NB * TT) / 64);   // (16, 512)
    proj_kernel<<<pgrid, 256, SM_TOTAL>>>(in_b, eps, out);

    scan_kernel<<<NBLK, 512, SM_TOTAL>>>(out);
}

// round 14
// speedup vs baseline: 2.7470x; 1.0031x over previous
#include <cuda_runtime.h>
#include <cuda_bf16.h>
#include <math.h>
#include <stdint.h>

#define NB 64
#define TT 512
#define NI 256
#define NH 1024
#define NOISEF 0.1f
#define NKS 8             // k-slices of 128
#define NTILE 16          // j-tiles of 64
#define NBLK 128

// ---- static device scratch ----
__device__ float g_h32[2][NB * NH];            // fp32 hidden state, double buf
__device__ __nv_bfloat16 g_hh[2][NB * NH];     // bf16 hi of h (planar)
__device__ __nv_bfloat16 g_hl[2][NB * NH];     // bf16 lo residual (planar)
__device__ float g_part[NKS][NB * NH];         // split-K slabs, PAIR layout [b/2][j][2]
__device__ float g_alpha[NH];
__device__ __nv_bfloat16 g_wthi[NH * NH];      // [j][k] = bf16_hi(W[k][j])
__device__ __nv_bfloat16 g_wtlo[NH * NH];      // [j][k] = residual
__device__ __nv_bfloat16 g_xhi[NB * TT * NI];  // bf16_hi(x) [r][k]
__device__ __nv_bfloat16 g_xlo[NB * TT * NI];
__device__ __nv_bfloat16 g_iwhi[NH * NI];      // bf16_hi(in_w) [j][k]
__device__ __nv_bfloat16 g_iwlo[NH * NI];
__device__ int g_cnt[NTILE];                   // slab arrivals per tile (monotonic)
__device__ int g_ecnt[NTILE];                  // epilogue parts per tile (monotonic)

// scan smem layout (272B-padded rows of 128 bf16)
#define SM_WHI 0
#define SM_WLO 17408
#define SM_BHI 34816
#define SM_BLO 52224
#define SM_TOTAL 69632
#define ROWB 272

// proj smem layout: x tile 128 rows, w tile 64 rows (hi/lo each)
#define PJ_XHI 0
#define PJ_XLO 34816
#define PJ_WHI 69632
#define PJ_WLO 87040
#define PJ_TOTAL 104448

static __device__ __forceinline__ uint32_t smem_u32(const void* p) {
    uint32_t a;
    asm("{ .reg .u64 t; cvta.to.shared.u64 t, %1; cvt.u32.u64 %0, t; }" : "=r"(a) : "l"(p));
    return a;
}
static __device__ __forceinline__ int ldacq(const int* p) {
    int v;
    asm volatile("ld.acquire.gpu.global.b32 %0, [%1];" : "=r"(v) : "l"(p) : "memory");
    return v;
}
static __device__ __forceinline__ void red_rel(int* p) {
    asm volatile("red.release.gpu.global.add.s32 [%0], 1;" :: "l"(p) : "memory");
}

#define LDSM4(r, a)                                                             \
    asm volatile("ldmatrix.sync.aligned.m8n8.x4.shared.b16 {%0,%1,%2,%3}, [%4];" \
        : "=r"((r)[0]), "=r"((r)[1]), "=r"((r)[2]), "=r"((r)[3]) : "r"(a))

#define MMA16816(d, a, b0, b1)                                                  \
    asm volatile("mma.sync.aligned.m16n8k16.row.col.f32.bf16.bf16.f32 "         \
        "{%0,%1,%2,%3}, {%4,%5,%6,%7}, {%8,%9}, {%0,%1,%2,%3};"                 \
        : "+f"((d)[0]), "+f"((d)[1]), "+f"((d)[2]), "+f"((d)[3])                \
        : "r"((a)[0]), "r"((a)[1]), "r"((a)[2]), "r"((a)[3]), "r"(b0), "r"(b1))

static __device__ __forceinline__ uint32_t bf2(float a, float b) {
    uint32_t r;
    asm("cvt.rn.bf16x2.f32 %0, %1, %2;" : "=r"(r) : "f"(b), "f"(a));
    return r;
}
static __device__ __forceinline__ float bf_lo(uint32_t u) { return __uint_as_float(u << 16); }
static __device__ __forceinline__ float bf_hi(uint32_t u) { return __uint_as_float(u & 0xFFFF0000u); }
static __device__ __forceinline__ float ftanh(float x) {
    float e = __expf(2.0f * x);
    return 1.0f - __fdividef(2.0f, e + 1.0f);
}

__global__ void init_kernel(const float* __restrict__ taus) {
    int idx = blockIdx.x * blockDim.x + threadIdx.x;
    if (idx < NB * NH) {
        g_h32[0][idx] = 0.0f;
        g_hh[0][idx] = __float2bfloat16(0.0f);
        g_hl[0][idx] = __float2bfloat16(0.0f);
    }
    if (idx < NH) {
        float s = 1.0f / (1.0f + expf(-taus[idx]));
        g_alpha[idx] = 10.0f / (s * 90.0f + 10.0f);
    }
    if (idx < NTILE) { g_cnt[idx] = 0; g_ecnt[idx] = 0; }
}

// elementwise bf16 hi/lo split for proj inputs
__global__ void split_kernel(const float* __restrict__ src, int which, int n4) {
    int idx = blockIdx.x * blockDim.x + threadIdx.x;
    if (idx >= n4) return;
    float4 v = ((const float4*)src)[idx];
    uint32_t h01 = bf2(v.x, v.y);
    uint32_t h23 = bf2(v.z, v.w);
    uint32_t l01 = bf2(v.x - bf_lo(h01), v.y - bf_hi(h01));
    uint32_t l23 = bf2(v.z - bf_lo(h23), v.w - bf_hi(h23));
    uint2* dh = which ? (uint2*)g_iwhi : (uint2*)g_xhi;
    uint2* dl = which ? (uint2*)g_iwlo : (uint2*)g_xlo;
    dh[idx] = make_uint2(h01, h23);
    dl[idx] = make_uint2(l01, l23);
}

// W [k][j] -> g_wthi/g_wtlo [j][k] bf16 split
__global__ void wsplit_kernel(const float* __restrict__ W) {
    __shared__ float t[32][33];
    int bk = blockIdx.x * 32;
    int bj = blockIdx.y * 32;
    int tx = threadIdx.x, ty = threadIdx.y;
    for (int i = ty; i < 32; i += 8) t[i][tx] = W[(bk + i) * NH + bj + tx];
    __syncthreads();
    for (int i = ty; i < 32; i += 8) {
        float v = t[tx][i];
        __nv_bfloat16 hi = __float2bfloat16(v);
        float r = v - __bfloat162float(hi);
        g_wthi[(bj + i) * NH + bk + tx] = hi;
        g_wtlo[(bj + i) * NH + bk + tx] = __float2bfloat16(r);
    }
}

// ---------------------------------------------------------------------------
// Input projection via HMMA split-bf16: 128r x 64j tile, 512 threads.
// Warp (16 total): wm = (w&7)*16 r-offset, wn = (w>>3)*32 j-offset.
// Inner mapping identical to the verified R12 kernel.
// ---------------------------------------------------------------------------
__global__ void __launch_bounds__(512) proj_kernel(
    const float* __restrict__ bias, const float* __restrict__ eps,
    float* __restrict__ out)
{
    extern __shared__ char smem[];
    const uint32_t sb = smem_u32(smem);
    const int tid = threadIdx.x;
    const int l = tid & 31, w = tid >> 5;
    const int j0 = blockIdx.x * 64;
    const int r0 = blockIdx.y * 128;
    const int wm = (w & 7) * 16;    // r offset of warp (0..112)
    const int wn = (w >> 3) * 32;   // j offset of warp (0 or 32)

    const uint32_t aHi = sb + PJ_XHI + (wm + (l & 15)) * ROWB + (l >> 4) * 16;
    const uint32_t aLo = aHi + (PJ_XLO - PJ_XHI);
    const uint32_t brow = wn + ((l >> 4) << 3) + (l & 7);
    const uint32_t boff = ((l >> 3) & 1) * 16;
    const uint32_t b0Hi = sb + PJ_WHI + brow * ROWB + boff;
    const uint32_t b1Hi = b0Hi + 16 * ROWB;
    const uint32_t b0Lo = b0Hi + (PJ_WLO - PJ_WHI);
    const uint32_t b1Lo = b1Hi + (PJ_WLO - PJ_WHI);

    // staging: x 128 rows (4 threads/row, 64B each), w 64 rows (8 threads/row, 32B each)
    const int xr = tid >> 2, xc = tid & 3;
    const int wr = tid >> 3, wc = tid & 7;

    float acc[4][4];
#pragma unroll
    for (int n = 0; n < 4; n++)
#pragma unroll
        for (int i = 0; i < 4; i++) acc[n][i] = 0.0f;

#pragma unroll
    for (int kc = 0; kc < 2; kc++) {
        const int kb = kc * 128;
        if (kc) __syncthreads();
        {
            const char* sxh = (const char*)(g_xhi + (size_t)(r0 + xr) * NI + kb) + xc * 64;
            const char* sxl = (const char*)(g_xlo + (size_t)(r0 + xr) * NI + kb) + xc * 64;
            char* dxh = smem + PJ_XHI + xr * ROWB + xc * 64;
            char* dxl = smem + PJ_XLO + xr * ROWB + xc * 64;
#pragma unroll
            for (int i = 0; i < 4; i++) {
                *(uint4*)(dxh + i * 16) = *(const uint4*)(sxh + i * 16);
                *(uint4*)(dxl + i * 16) = *(const uint4*)(sxl + i * 16);
            }
            const char* swh = (const char*)(g_iwhi + (size_t)(j0 + wr) * NI + kb) + wc * 32;
            const char* swl = (const char*)(g_iwlo + (size_t)(j0 + wr) * NI + kb) + wc * 32;
            char* dwh = smem + PJ_WHI + wr * ROWB + wc * 32;
            char* dwl = smem + PJ_WLO + wr * ROWB + wc * 32;
            *(uint4*)dwh = *(const uint4*)swh;
            *(uint4*)(dwh + 16) = *(const uint4*)(swh + 16);
            *(uint4*)dwl = *(const uint4*)swl;
            *(uint4*)(dwl + 16) = *(const uint4*)(swl + 16);
        }
        __syncthreads();

#pragma unroll
        for (int kk = 0; kk < 8; kk++) {
            const uint32_t off = kk * 32;
            uint32_t ah[4], al4[4], bh0[4], bh1[4], bl0[4], bl1[4];
            LDSM4(ah, aHi + off);
            LDSM4(al4, aLo + off);
            LDSM4(bh0, b0Hi + off);
            LDSM4(bh1, b1Hi + off);
            LDSM4(bl0, b0Lo + off);
            LDSM4(bl1, b1Lo + off);
            MMA16816(acc[0], ah, bh0[0], bh0[1]);
            MMA16816(acc[1], ah, bh0[2], bh0[3]);
            MMA16816(acc[2], ah, bh1[0], bh1[1]);
            MMA16816(acc[3], ah, bh1[2], bh1[3]);
            MMA16816(acc[0], ah, bl0[0], bl0[1]);
            MMA16816(acc[1], ah, bl0[2], bl0[3]);
            MMA16816(acc[2], ah, bl1[0], bl1[1]);
            MMA16816(acc[3], ah, bl1[2], bl1[3]);
            MMA16816(acc[0], al4, bh0[0], bh0[1]);
            MMA16816(acc[1], al4, bh0[2], bh0[3]);
            MMA16816(acc[2], al4, bh1[0], bh1[1]);
            MMA16816(acc[3], al4, bh1[2], bh1[3]);
        }
    }

    const int er = r0 + wm + (l >> 2);
    const int ejc = j0 + wn + 2 * (l & 3);
#pragma unroll
    for (int n = 0; n < 4; n++) {
        int j = ejc + 8 * n;
        float2 bi = *(const float2*)(bias + j);
        long off0 = (long)er * NH + j;
        float2 ev0 = *(const float2*)(eps + off0);
        *(float2*)(out + off0) = make_float2(acc[n][0] + bi.x + NOISEF * ev0.x,
                                             acc[n][1] + bi.y + NOISEF * ev0.y);
        long off1 = (long)(er + 8) * NH + j;
        float2 ev1 = *(const float2*)(eps + off1);
        *(float2*)(out + off1) = make_float2(acc[n][2] + bi.x + NOISEF * ev1.x,
                                             acc[n][3] + bi.y + NOISEF * ev1.y);
    }
}

// ---------------------------------------------------------------------------
// Persistent scan: 128 blocks x 512 threads (16 warps, 4/SMSP).
// Point-to-point release/acquire sync; planar bf16 staging;
// epilogue: one (b, j) cell per thread (512 cells/block).
// ---------------------------------------------------------------------------
__global__ void __launch_bounds__(512, 1) scan_kernel(float* __restrict__ out)
{
    extern __shared__ char smem[];
    const uint32_t sb = smem_u32(smem);
    const int tid = threadIdx.x;
    const int l = tid & 31, w = tid >> 5;
    const int nt = blockIdx.x & 15;
    const int ks = blockIdx.x >> 4;
    const int j0 = nt * 64;
    const int k0 = ks * 128;

    // Load W^T hi/lo tile [64 j][128 k] into padded smem (once)
    {
        int r = tid >> 3, c = tid & 7;
        *(uint4*)(smem + SM_WHI + r * ROWB + c * 32) =
            *(const uint4*)((const char*)(g_wthi + (size_t)(j0 + r) * NH + k0) + c * 32);
        *(uint4*)(smem + SM_WHI + r * ROWB + c * 32 + 16) =
            *(const uint4*)((const char*)(g_wthi + (size_t)(j0 + r) * NH + k0) + c * 32 + 16);
        *(uint4*)(smem + SM_WLO + r * ROWB + c * 32) =
            *(const uint4*)((const char*)(g_wtlo + (size_t)(j0 + r) * NH + k0) + c * 32);
        *(uint4*)(smem + SM_WLO + r * ROWB + c * 32 + 16) =
            *(const uint4*)((const char*)(g_wtlo + (size_t)(j0 + r) * NH + k0) + c * 32 + 16);
    }

    // 16-warp partition: warp covers 16 j x 16 b
    const int wm = (w & 3) * 16;    // j offset
    const int wn = (w >> 2) * 16;   // b offset
    const uint32_t aHi = sb + SM_WHI + (wm + (l & 15)) * ROWB + (l >> 4) * 16;
    const uint32_t aLo = aHi + (SM_WLO - SM_WHI);
    const uint32_t brow = wn + ((l >> 4) << 3) + (l & 7);
    const uint32_t boff = ((l >> 3) & 1) * 16;
    const uint32_t b0Hi = sb + SM_BHI + brow * ROWB + boff;
    const uint32_t b0Lo = b0Hi + (SM_BLO - SM_BHI);

    __syncthreads();

    // Hoist A fragments (W tile) into registers
    uint32_t Ah[8][4], Al[8][4];
#pragma unroll
    for (int kk = 0; kk < 8; kk++) {
        LDSM4(Ah[kk], aHi + kk * 32);
        LDSM4(Al[kk], aLo + kk * 32);
    }

    // slab-store coords (pair layout [b/2][j][2])
    const int sj0 = j0 + wm + (l >> 2);
    const int sb0 = wn + 2 * (l & 3);

    // epilogue coords: one cell per thread: b in [8ks, 8ks+8), 64 j of tile nt
    const int ej = j0 + (tid & 63);
    const int eb = 8 * ks + (tid >> 6);
    const float alf = g_alpha[ej];

    // staging coords: 512 threads, each 16 k-values of one b-row (hi+lo)
    const int stb = tid >> 3, stc = tid & 7;
    char* dBh = smem + SM_BHI + stb * ROWB + stc * 32;
    char* dBl = smem + SM_BLO + stb * ROWB + stc * 32;

    for (int t = 0; t < TT; t++) {
        // early prefetch of pre-activation (only this block touches it)
        const long o0 = ((long)eb * TT + t) * NH + ej;
        const float p0 = out[o0];

        // point-to-point waits (3 warps poll in parallel, acquire loads)
        if (t > 0) {
            const int tgt = 8 * t;
            if (tid == 0)  { while (ldacq(&g_ecnt[2 * ks]) < tgt) __nanosleep(16); }
            if (tid == 32) { while (ldacq(&g_ecnt[2 * ks + 1]) < tgt) __nanosleep(16); }
            if (tid == 64) { while (ldacq(&g_ecnt[nt]) < tgt) __nanosleep(16); }
            __syncthreads();
        }

        // stage h slice: planar hi/lo, pure LDG.128 -> STS.128
        {
            const char* sh = (const char*)(g_hh[t & 1] + stb * NH + k0) + stc * 32;
            const char* sl = (const char*)(g_hl[t & 1] + stb * NH + k0) + stc * 32;
            uint4 v0 = __ldcg((const uint4*)sh);
            uint4 v1 = __ldcg((const uint4*)(sh + 16));
            uint4 v2 = __ldcg((const uint4*)sl);
            uint4 v3 = __ldcg((const uint4*)(sl + 16));
            *(uint4*)dBh = v0;
            *(uint4*)(dBh + 16) = v1;
            *(uint4*)dBl = v2;
            *(uint4*)(dBl + 16) = v3;
        }

        // prefetch step t-1 hidden state (covered by ecnt waits)
        const float h0 = __ldcg(&g_h32[t & 1][eb * NH + ej]);

        __syncthreads();

        // GEMM: 8 k-steps of 16, split-bf16 (3 products), A in registers
        float acc[2][4];
#pragma unroll
        for (int n = 0; n < 2; n++)
#pragma unroll
            for (int i = 0; i < 4; i++) acc[n][i] = 0.0f;

#pragma unroll
        for (int kk = 0; kk < 8; kk++) {
            const uint32_t off = kk * 32;
            uint32_t bh0[4], bl0[4];
            LDSM4(bh0, b0Hi + off);
            LDSM4(bl0, b0Lo + off);
            MMA16816(acc[0], Ah[kk], bh0[0], bh0[1]);
            MMA16816(acc[1], Ah[kk], bh0[2], bh0[3]);
            MMA16816(acc[0], Ah[kk], bl0[0], bl0[1]);
            MMA16816(acc[1], Ah[kk], bl0[2], bl0[3]);
            MMA16816(acc[0], Al[kk], bh0[0], bh0[1]);
            MMA16816(acc[1], Al[kk], bh0[2], bh0[3]);
        }

        // store slab, pair layout
        {
            float* part = g_part[ks];
#pragma unroll
            for (int n = 0; n < 2; n++) {
                int pr = (sb0 + 8 * n) >> 1;
                *(float2*)(part + (size_t)pr * 2048 + sj0 * 2) =
                    make_float2(acc[n][0], acc[n][1]);
                *(float2*)(part + (size_t)pr * 2048 + (sj0 + 8) * 2) =
                    make_float2(acc[n][2], acc[n][3]);
            }
        }

        // release slab writes, rendezvous on tile nt's 8 slabs
        __syncthreads();
        if (tid == 0) {
            red_rel(&g_cnt[nt]);
            while (ldacq(&g_cnt[nt]) < 8 * (t + 1)) __nanosleep(16);
        }
        __syncthreads();

        // distributed epilogue: one cell per thread
        {
            const size_t poff = (size_t)(eb >> 1) * 2048 + ej * 2 + (eb & 1);
            float s0 = 0.0f;
#pragma unroll
            for (int q = 0; q < NKS; q++) s0 += __ldcg(&g_part[q][poff]);
            float n0 = (1.0f - alf) * h0 + alf * ftanh(p0 + s0);
            out[o0] = n0;
            g_h32[(t + 1) & 1][eb * NH + ej] = n0;
            __nv_bfloat16 b0 = __float2bfloat16(n0);
            g_hh[(t + 1) & 1][eb * NH + ej] = b0;
            g_hl[(t + 1) & 1][eb * NH + ej] = __float2bfloat16(n0 - __bfloat162float(b0));
        }

        // release epilogue writes for step t of tile nt
        __syncthreads();
        if (tid == 0) red_rel(&g_ecnt[nt]);
    }
}

extern "C" void kernel_launch(void* const* d_in, const int* in_sizes, int n_in,
                              void* d_out, int out_size) {
    const float* x    = (const float*)d_in[0];  // [B,T,I]
    const float* eps  = (const float*)d_in[1];  // [B,T,H]
    const float* in_w = (const float*)d_in[2];  // [H,I]
    const float* in_b = (const float*)d_in[3];  // [H]
    const float* W    = (const float*)d_in[4];  // [H,H]
    const float* taus = (const float*)d_in[5];  // [H]
    float* out = (float*)d_out;                 // [B,T,H]

    static int attr_done = 0;
    if (!attr_done) {
        cudaFuncSetAttribute(scan_kernel, cudaFuncAttributeMaxDynamicSharedMemorySize, SM_TOTAL);
        cudaFuncSetAttribute(proj_kernel, cudaFuncAttributeMaxDynamicSharedMemorySize, PJ_TOTAL);
        attr_done = 1;
    }

    init_kernel<<<(NB * NH + 255) / 256, 256>>>(taus);
    wsplit_kernel<<<dim3(NH / 32, NH / 32), dim3(32, 8)>>>(W);
    split_kernel<<<(NB * TT * NI / 4 + 255) / 256, 256>>>(x, 0, NB * TT * NI / 4);
    split_kernel<<<(NH * NI / 4 + 255) / 256, 256>>>(in_w, 1, NH * NI / 4);

    dim3 pgrid(NH / 64, (NB * TT) / 128);   // (16, 256)
    proj_kernel<<<pgrid, 512, PJ_TOTAL>>>(in_b, eps, out);

    scan_kernel<<<NBLK, 512, SM_TOTAL>>>(out);
}

// round 15
// speedup vs baseline: 3.1015x; 1.1290x over previous
#include <cuda_runtime.h>
#include <cuda_bf16.h>
#include <cuda_fp16.h>
#include <math.h>
#include <stdint.h>

#define NB 64
#define TT 512
#define NI 256
#define NH 1024
#define NOISEF 0.1f
#define NKS 8             // k-slices of 128
#define NTILE 16          // j-tiles of 64
#define NBLK 128

// ---- static device scratch ----
__device__ float g_h32[2][NB * NH];            // fp32 hidden state, double buf
__device__ __half g_hf[2][NB * NH];            // fp16 h (single, planar)
__device__ float g_part[NKS][NB * NH];         // split-K slabs, PAIR layout [b/2][j][2]
__device__ float g_alpha[NH];
__device__ __half g_wfhi[NH * NH];             // [j][k] = fp16_hi(W[k][j])
__device__ __half g_wflo[NH * NH];             // [j][k] = fp16 residual
__device__ __nv_bfloat16 g_xhi[NB * TT * NI];  // bf16_hi(x) [r][k]  (proj)
__device__ __nv_bfloat16 g_xlo[NB * TT * NI];
__device__ __nv_bfloat16 g_iwhi[NH * NI];      // bf16_hi(in_w) [j][k] (proj)
__device__ __nv_bfloat16 g_iwlo[NH * NI];
__device__ int g_cnt[NTILE];                   // slab arrivals per tile (monotonic)
__device__ int g_ecnt[NTILE];                  // epilogue parts per tile (monotonic)

// scan smem layout (272B-padded rows of 128 fp16)
#define SM_WHI 0
#define SM_WLO 17408
#define SM_B   34816
#define SM_TOTAL 52224
#define ROWB 272

// proj smem layout: x tile 128 rows, w tile 64 rows (hi/lo each)
#define PJ_XHI 0
#define PJ_XLO 34816
#define PJ_WHI 69632
#define PJ_WLO 87040
#define PJ_TOTAL 104448

static __device__ __forceinline__ uint32_t smem_u32(const void* p) {
    uint32_t a;
    asm("{ .reg .u64 t; cvta.to.shared.u64 t, %1; cvt.u32.u64 %0, t; }" : "=r"(a) : "l"(p));
    return a;
}
static __device__ __forceinline__ int ldacq(const int* p) {
    int v;
    asm volatile("ld.acquire.gpu.global.b32 %0, [%1];" : "=r"(v) : "l"(p) : "memory");
    return v;
}
static __device__ __forceinline__ void red_rel(int* p) {
    asm volatile("red.release.gpu.global.add.s32 [%0], 1;" :: "l"(p) : "memory");
}

#define LDSM4(r, a)                                                             \
    asm volatile("ldmatrix.sync.aligned.m8n8.x4.shared.b16 {%0,%1,%2,%3}, [%4];" \
        : "=r"((r)[0]), "=r"((r)[1]), "=r"((r)[2]), "=r"((r)[3]) : "r"(a))

#define MMA16816(d, a, b0, b1)                                                  \
    asm volatile("mma.sync.aligned.m16n8k16.row.col.f32.bf16.bf16.f32 "         \
        "{%0,%1,%2,%3}, {%4,%5,%6,%7}, {%8,%9}, {%0,%1,%2,%3};"                 \
        : "+f"((d)[0]), "+f"((d)[1]), "+f"((d)[2]), "+f"((d)[3])                \
        : "r"((a)[0]), "r"((a)[1]), "r"((a)[2]), "r"((a)[3]), "r"(b0), "r"(b1))

#define MMAF16816(d, a, b0, b1)                                                 \
    asm volatile("mma.sync.aligned.m16n8k16.row.col.f32.f16.f16.f32 "           \
        "{%0,%1,%2,%3}, {%4,%5,%6,%7}, {%8,%9}, {%0,%1,%2,%3};"                 \
        : "+f"((d)[0]), "+f"((d)[1]), "+f"((d)[2]), "+f"((d)[3])                \
        : "r"((a)[0]), "r"((a)[1]), "r"((a)[2]), "r"((a)[3]), "r"(b0), "r"(b1))

static __device__ __forceinline__ uint32_t bf2(float a, float b) {
    uint32_t r;
    asm("cvt.rn.bf16x2.f32 %0, %1, %2;" : "=r"(r) : "f"(b), "f"(a));
    return r;
}
static __device__ __forceinline__ float bf_lo(uint32_t u) { return __uint_as_float(u << 16); }
static __device__ __forceinline__ float bf_hi(uint32_t u) { return __uint_as_float(u & 0xFFFF0000u); }
static __device__ __forceinline__ float ftanh(float x) {
    float e = __expf(2.0f * x);
    return 1.0f - __fdividef(2.0f, e + 1.0f);
}

__global__ void init_kernel(const float* __restrict__ taus) {
    int idx = blockIdx.x * blockDim.x + threadIdx.x;
    if (idx < NB * NH) {
        g_h32[0][idx] = 0.0f;
        g_hf[0][idx] = __float2half(0.0f);
    }
    if (idx < NH) {
        float s = 1.0f / (1.0f + expf(-taus[idx]));
        g_alpha[idx] = 10.0f / (s * 90.0f + 10.0f);
    }
    if (idx < NTILE) { g_cnt[idx] = 0; g_ecnt[idx] = 0; }
}

// elementwise bf16 hi/lo split for proj inputs
__global__ void split_kernel(const float* __restrict__ src, int which, int n4) {
    int idx = blockIdx.x * blockDim.x + threadIdx.x;
    if (idx >= n4) return;
    float4 v = ((const float4*)src)[idx];
    uint32_t h01 = bf2(v.x, v.y);
    uint32_t h23 = bf2(v.z, v.w);
    uint32_t l01 = bf2(v.x - bf_lo(h01), v.y - bf_hi(h01));
    uint32_t l23 = bf2(v.z - bf_lo(h23), v.w - bf_hi(h23));
    uint2* dh = which ? (uint2*)g_iwhi : (uint2*)g_xhi;
    uint2* dl = which ? (uint2*)g_iwlo : (uint2*)g_xlo;
    dh[idx] = make_uint2(h01, h23);
    dl[idx] = make_uint2(l01, l23);
}

// W [k][j] -> g_wfhi/g_wflo [j][k] fp16 split (exact to ~2^-22)
__global__ void wsplit_kernel(const float* __restrict__ W) {
    __shared__ float t[32][33];
    int bk = blockIdx.x * 32;
    int bj = blockIdx.y * 32;
    int tx = threadIdx.x, ty = threadIdx.y;
    for (int i = ty; i < 32; i += 8) t[i][tx] = W[(bk + i) * NH + bj + tx];
    __syncthreads();
    for (int i = ty; i < 32; i += 8) {
        float v = t[tx][i];
        __half hi = __float2half(v);
        float r = v - __half2float(hi);
        g_wfhi[(bj + i) * NH + bk + tx] = hi;
        g_wflo[(bj + i) * NH + bk + tx] = __float2half(r);
    }
}

// ---------------------------------------------------------------------------
// Input projection via HMMA split-bf16 (proven R13/R14 kernel, unchanged)
// ---------------------------------------------------------------------------
__global__ void __launch_bounds__(512) proj_kernel(
    const float* __restrict__ bias, const float* __restrict__ eps,
    float* __restrict__ out)
{
    extern __shared__ char smem[];
    const uint32_t sb = smem_u32(smem);
    const int tid = threadIdx.x;
    const int l = tid & 31, w = tid >> 5;
    const int j0 = blockIdx.x * 64;
    const int r0 = blockIdx.y * 128;
    const int wm = (w & 7) * 16;
    const int wn = (w >> 3) * 32;

    const uint32_t aHi = sb + PJ_XHI + (wm + (l & 15)) * ROWB + (l >> 4) * 16;
    const uint32_t aLo = aHi + (PJ_XLO - PJ_XHI);
    const uint32_t brow = wn + ((l >> 4) << 3) + (l & 7);
    const uint32_t boff = ((l >> 3) & 1) * 16;
    const uint32_t b0Hi = sb + PJ_WHI + brow * ROWB + boff;
    const uint32_t b1Hi = b0Hi + 16 * ROWB;
    const uint32_t b0Lo = b0Hi + (PJ_WLO - PJ_WHI);
    const uint32_t b1Lo = b1Hi + (PJ_WLO - PJ_WHI);

    const int xr = tid >> 2, xc = tid & 3;
    const int wr = tid >> 3, wc = tid & 7;

    float acc[4][4];
#pragma unroll
    for (int n = 0; n < 4; n++)
#pragma unroll
        for (int i = 0; i < 4; i++) acc[n][i] = 0.0f;

#pragma unroll
    for (int kc = 0; kc < 2; kc++) {
        const int kb = kc * 128;
        if (kc) __syncthreads();
        {
            const char* sxh = (const char*)(g_xhi + (size_t)(r0 + xr) * NI + kb) + xc * 64;
            const char* sxl = (const char*)(g_xlo + (size_t)(r0 + xr) * NI + kb) + xc * 64;
            char* dxh = smem + PJ_XHI + xr * ROWB + xc * 64;
            char* dxl = smem + PJ_XLO + xr * ROWB + xc * 64;
#pragma unroll
            for (int i = 0; i < 4; i++) {
                *(uint4*)(dxh + i * 16) = *(const uint4*)(sxh + i * 16);
                *(uint4*)(dxl + i * 16) = *(const uint4*)(sxl + i * 16);
            }
            const char* swh = (const char*)(g_iwhi + (size_t)(j0 + wr) * NI + kb) + wc * 32;
            const char* swl = (const char*)(g_iwlo + (size_t)(j0 + wr) * NI + kb) + wc * 32;
            char* dwh = smem + PJ_WHI + wr * ROWB + wc * 32;
            char* dwl = smem + PJ_WLO + wr * ROWB + wc * 32;
            *(uint4*)dwh = *(const uint4*)swh;
            *(uint4*)(dwh + 16) = *(const uint4*)(swh + 16);
            *(uint4*)dwl = *(const uint4*)swl;
            *(uint4*)(dwl + 16) = *(const uint4*)(swl + 16);
        }
        __syncthreads();

#pragma unroll
        for (int kk = 0; kk < 8; kk++) {
            const uint32_t off = kk * 32;
            uint32_t ah[4], al4[4], bh0[4], bh1[4], bl0[4], bl1[4];
            LDSM4(ah, aHi + off);
            LDSM4(al4, aLo + off);
            LDSM4(bh0, b0Hi + off);
            LDSM4(bh1, b1Hi + off);
            LDSM4(bl0, b0Lo + off);
            LDSM4(bl1, b1Lo + off);
            MMA16816(acc[0], ah, bh0[0], bh0[1]);
            MMA16816(acc[1], ah, bh0[2], bh0[3]);
            MMA16816(acc[2], ah, bh1[0], bh1[1]);
            MMA16816(acc[3], ah, bh1[2], bh1[3]);
            MMA16816(acc[0], ah, bl0[0], bl0[1]);
            MMA16816(acc[1], ah, bl0[2], bl0[3]);
            MMA16816(acc[2], ah, bl1[0], bl1[1]);
            MMA16816(acc[3], ah, bl1[2], bl1[3]);
            MMA16816(acc[0], al4, bh0[0], bh0[1]);
            MMA16816(acc[1], al4, bh0[2], bh0[3]);
            MMA16816(acc[2], al4, bh1[0], bh1[1]);
            MMA16816(acc[3], al4, bh1[2], bh1[3]);
        }
    }

    const int er = r0 + wm + (l >> 2);
    const int ejc = j0 + wn + 2 * (l & 3);
#pragma unroll
    for (int n = 0; n < 4; n++) {
        int j = ejc + 8 * n;
        float2 bi = *(const float2*)(bias + j);
        long off0 = (long)er * NH + j;
        float2 ev0 = *(const float2*)(eps + off0);
        *(float2*)(out + off0) = make_float2(acc[n][0] + bi.x + NOISEF * ev0.x,
                                             acc[n][1] + bi.y + NOISEF * ev0.y);
        long off1 = (long)(er + 8) * NH + j;
        float2 ev1 = *(const float2*)(eps + off1);
        *(float2*)(out + off1) = make_float2(acc[n][2] + bi.x + NOISEF * ev1.x,
                                             acc[n][3] + bi.y + NOISEF * ev1.y);
    }
}

// ---------------------------------------------------------------------------
// Persistent scan: 128 blocks x 512 threads. fp16 split-W 2-product HMMA.
// Point-to-point release/acquire sync; single planar fp16 h staging.
// ---------------------------------------------------------------------------
__global__ void __launch_bounds__(512, 1) scan_kernel(float* __restrict__ out)
{
    extern __shared__ char smem[];
    const uint32_t sb = smem_u32(smem);
    const int tid = threadIdx.x;
    const int l = tid & 31, w = tid >> 5;
    const int nt = blockIdx.x & 15;
    const int ks = blockIdx.x >> 4;
    const int j0 = nt * 64;
    const int k0 = ks * 128;

    // Load W^T fp16 hi/lo tile [64 j][128 k] into padded smem (once)
    {
        int r = tid >> 3, c = tid & 7;
        *(uint4*)(smem + SM_WHI + r * ROWB + c * 32) =
            *(const uint4*)((const char*)(g_wfhi + (size_t)(j0 + r) * NH + k0) + c * 32);
        *(uint4*)(smem + SM_WHI + r * ROWB + c * 32 + 16) =
            *(const uint4*)((const char*)(g_wfhi + (size_t)(j0 + r) * NH + k0) + c * 32 + 16);
        *(uint4*)(smem + SM_WLO + r * ROWB + c * 32) =
            *(const uint4*)((const char*)(g_wflo + (size_t)(j0 + r) * NH + k0) + c * 32);
        *(uint4*)(smem + SM_WLO + r * ROWB + c * 32 + 16) =
            *(const uint4*)((const char*)(g_wflo + (size_t)(j0 + r) * NH + k0) + c * 32 + 16);
    }

    // 16-warp partition: warp covers 16 j x 16 b
    const int wm = (w & 3) * 16;    // j offset
    const int wn = (w >> 2) * 16;   // b offset
    const uint32_t aHi = sb + SM_WHI + (wm + (l & 15)) * ROWB + (l >> 4) * 16;
    const uint32_t aLo = aHi + (SM_WLO - SM_WHI);
    const uint32_t brow = wn + ((l >> 4) << 3) + (l & 7);
    const uint32_t boff = ((l >> 3) & 1) * 16;
    const uint32_t b0 = sb + SM_B + brow * ROWB + boff;

    __syncthreads();

    // Hoist A fragments (W fp16 hi/lo) into registers
    uint32_t Ah[8][4], Al[8][4];
#pragma unroll
    for (int kk = 0; kk < 8; kk++) {
        LDSM4(Ah[kk], aHi + kk * 32);
        LDSM4(Al[kk], aLo + kk * 32);
    }

    // slab-store coords (pair layout [b/2][j][2])
    const int sj0 = j0 + wm + (l >> 2);
    const int sb0 = wn + 2 * (l & 3);

    // epilogue coords: one cell per thread: b in [8ks, 8ks+8), 64 j of tile nt
    const int ej = j0 + (tid & 63);
    const int eb = 8 * ks + (tid >> 6);
    const float alf = g_alpha[ej];

    // staging coords: 512 threads, each 16 fp16 of one b-row (32B)
    const int stb = tid >> 3, stc = tid & 7;
    char* dB = smem + SM_B + stb * ROWB + stc * 32;

    for (int t = 0; t < TT; t++) {
        // early prefetch of pre-activation (only this block touches it)
        const long o0 = ((long)eb * TT + t) * NH + ej;
        const float p0 = out[o0];

        // point-to-point waits (3 warps poll in parallel, acquire loads)
        if (t > 0) {
            const int tgt = 8 * t;
            if (tid == 0)  { while (ldacq(&g_ecnt[2 * ks]) < tgt) __nanosleep(16); }
            if (tid == 32) { while (ldacq(&g_ecnt[2 * ks + 1]) < tgt) __nanosleep(16); }
            if (tid == 64) { while (ldacq(&g_ecnt[nt]) < tgt) __nanosleep(16); }
            __syncthreads();
        }

        // stage h slice: single planar fp16, pure LDG.128 -> STS.128
        {
            const char* sh = (const char*)(g_hf[t & 1] + stb * NH + k0) + stc * 32;
            uint4 v0 = __ldcg((const uint4*)sh);
            uint4 v1 = __ldcg((const uint4*)(sh + 16));
            *(uint4*)dB = v0;
            *(uint4*)(dB + 16) = v1;
        }

        // prefetch step t-1 hidden state (covered by ecnt waits)
        const float h0 = __ldcg(&g_h32[t & 1][eb * NH + ej]);

        __syncthreads();

        // GEMM: 8 k-steps of 16, fp16 2-product, A in registers
        float acc[2][4];
#pragma unroll
        for (int n = 0; n < 2; n++)
#pragma unroll
            for (int i = 0; i < 4; i++) acc[n][i] = 0.0f;

#pragma unroll
        for (int kk = 0; kk < 8; kk++) {
            uint32_t bb[4];
            LDSM4(bb, b0 + kk * 32);
            MMAF16816(acc[0], Ah[kk], bb[0], bb[1]);
            MMAF16816(acc[1], Ah[kk], bb[2], bb[3]);
            MMAF16816(acc[0], Al[kk], bb[0], bb[1]);
            MMAF16816(acc[1], Al[kk], bb[2], bb[3]);
        }

        // store slab, pair layout
        {
            float* part = g_part[ks];
#pragma unroll
            for (int n = 0; n < 2; n++) {
                int pr = (sb0 + 8 * n) >> 1;
                *(float2*)(part + (size_t)pr * 2048 + sj0 * 2) =
                    make_float2(acc[n][0], acc[n][1]);
                *(float2*)(part + (size_t)pr * 2048 + (sj0 + 8) * 2) =
                    make_float2(acc[n][2], acc[n][3]);
            }
        }

        // release slab writes, rendezvous on tile nt's 8 slabs
        __syncthreads();
        if (tid == 0) {
            red_rel(&g_cnt[nt]);
            while (ldacq(&g_cnt[nt]) < 8 * (t + 1)) __nanosleep(16);
        }
        __syncthreads();

        // distributed epilogue: one cell per thread
        {
            const size_t poff = (size_t)(eb >> 1) * 2048 + ej * 2 + (eb & 1);
            float s0 = 0.0f;
#pragma unroll
            for (int q = 0; q < NKS; q++) s0 += __ldcg(&g_part[q][poff]);
            float n0 = (1.0f - alf) * h0 + alf * ftanh(p0 + s0);
            out[o0] = n0;
            g_h32[(t + 1) & 1][eb * NH + ej] = n0;
            g_hf[(t + 1) & 1][eb * NH + ej] = __float2half(n0);
        }

        // release epilogue writes for step t of tile nt
        __syncthreads();
        if (tid == 0) red_rel(&g_ecnt[nt]);
    }
}

extern "C" void kernel_launch(void* const* d_in, const int* in_sizes, int n_in,
                              void* d_out, int out_size) {
    const float* x    = (const float*)d_in[0];  // [B,T,I]
    const float* eps  = (const float*)d_in[1];  // [B,T,H]
    const float* in_w = (const float*)d_in[2];  // [H,I]
    const float* in_b = (const float*)d_in[3];  // [H]
    const float* W    = (const float*)d_in[4];  // [H,H]
    const float* taus = (const float*)d_in[5];  // [H]
    float* out = (float*)d_out;                 // [B,T,H]

    static int attr_done = 0;
    if (!attr_done) {
        cudaFuncSetAttribute(scan_kernel, cudaFuncAttributeMaxDynamicSharedMemorySize, SM_TOTAL);
        cudaFuncSetAttribute(proj_kernel, cudaFuncAttributeMaxDynamicSharedMemorySize, PJ_TOTAL);
        attr_done = 1;
    }

    init_kernel<<<(NB * NH + 255) / 256, 256>>>(taus);
    wsplit_kernel<<<dim3(NH / 32, NH / 32), dim3(32, 8)>>>(W);
    split_kernel<<<(NB * TT * NI / 4 + 255) / 256, 256>>>(x, 0, NB * TT * NI / 4);
    split_kernel<<<(NH * NI / 4 + 255) / 256, 256>>>(in_w, 1, NH * NI / 4);

    dim3 pgrid(NH / 64, (NB * TT) / 128);   // (16, 256)
    proj_kernel<<<pgrid, 512, PJ_TOTAL>>>(in_b, eps, out);

    scan_kernel<<<NBLK, 512, SM_TOTAL>>>(out);
}

// round 16
// speedup vs baseline: 3.3797x; 1.0897x over previous
#include <cuda_runtime.h>
#include <cuda_fp16.h>
#include <math.h>
#include <stdint.h>

#define NB 64
#define TT 512
#define NI 256
#define NH 1024
#define NOISEF 0.1f
#define NKS 8             // k-slices of 128
#define NTILE 16          // j-tiles of 64
#define NBLK 128

// ---- static device scratch ----
__device__ float g_h32[2][NB * NH];            // fp32 hidden state, double buf
__device__ __half g_hf[2][NB * NH];            // fp16 h (single, planar)
__device__ float g_part[NKS][NB * NH];         // split-K slabs, PAIR layout [b/2][j][2]
__device__ float g_alpha[NH];
__device__ __half g_wf[NH * NH];               // [j][k] = fp16(W[k][j]) single
__device__ __half g_xf[NB * TT * NI];          // fp16(x) [r][k]  (proj, single)
__device__ __half g_iwh[NH * NI];              // fp16_hi(in_w) [j][k] (proj)
__device__ __half g_iwl[NH * NI];              // fp16 residual
__device__ int g_cnt[NTILE];                   // slab arrivals per tile (monotonic)
__device__ int g_ecnt[NTILE];                  // epilogue parts per tile (monotonic)

// scan smem layout (272B-padded rows of 128 fp16)
#define SM_W   0
#define SM_B   17408
#define SM_TOTAL 34816
#define ROWB 272

// proj smem layout: x tile 128 rows (single), w tile 64 rows (hi/lo)
#define PJ_X   0
#define PJ_WHI 34816
#define PJ_WLO 52224
#define PJ_TOTAL 69632

static __device__ __forceinline__ uint32_t smem_u32(const void* p) {
    uint32_t a;
    asm("{ .reg .u64 t; cvta.to.shared.u64 t, %1; cvt.u32.u64 %0, t; }" : "=r"(a) : "l"(p));
    return a;
}
static __device__ __forceinline__ int ldacq(const int* p) {
    int v;
    asm volatile("ld.acquire.gpu.global.b32 %0, [%1];" : "=r"(v) : "l"(p) : "memory");
    return v;
}
static __device__ __forceinline__ void red_rel(int* p) {
    asm volatile("red.release.gpu.global.add.s32 [%0], 1;" :: "l"(p) : "memory");
}

#define LDSM4(r, a)                                                             \
    asm volatile("ldmatrix.sync.aligned.m8n8.x4.shared.b16 {%0,%1,%2,%3}, [%4];" \
        : "=r"((r)[0]), "=r"((r)[1]), "=r"((r)[2]), "=r"((r)[3]) : "r"(a))

#define MMAF16816(d, a, b0, b1)                                                 \
    asm volatile("mma.sync.aligned.m16n8k16.row.col.f32.f16.f16.f32 "           \
        "{%0,%1,%2,%3}, {%4,%5,%6,%7}, {%8,%9}, {%0,%1,%2,%3};"                 \
        : "+f"((d)[0]), "+f"((d)[1]), "+f"((d)[2]), "+f"((d)[3])                \
        : "r"((a)[0]), "r"((a)[1]), "r"((a)[2]), "r"((a)[3]), "r"(b0), "r"(b1))

static __device__ __forceinline__ uint32_t h2u(__half a, __half b) {
    __half2 h = __halves2half2(a, b);
    return *reinterpret_cast<uint32_t*>(&h);
}
static __device__ __forceinline__ float ftanh(float x) {
    float e = __expf(2.0f * x);
    return 1.0f - __fdividef(2.0f, e + 1.0f);
}

__global__ void init_kernel(const float* __restrict__ taus) {
    int idx = blockIdx.x * blockDim.x + threadIdx.x;
    if (idx < NB * NH) {
        g_h32[0][idx] = 0.0f;
        g_hf[0][idx] = __float2half(0.0f);
    }
    if (idx < NH) {
        float s = 1.0f / (1.0f + expf(-taus[idx]));
        g_alpha[idx] = 10.0f / (s * 90.0f + 10.0f);
    }
    if (idx < NTILE) { g_cnt[idx] = 0; g_ecnt[idx] = 0; }
}

// x -> single fp16
__global__ void splitx_kernel(const float* __restrict__ src, int n4) {
    int idx = blockIdx.x * blockDim.x + threadIdx.x;
    if (idx >= n4) return;
    float4 v = ((const float4*)src)[idx];
    uint32_t u0 = h2u(__float2half(v.x), __float2half(v.y));
    uint32_t u1 = h2u(__float2half(v.z), __float2half(v.w));
    ((uint2*)g_xf)[idx] = make_uint2(u0, u1);
}

// in_w -> fp16 hi/lo split
__global__ void splitw_kernel(const float* __restrict__ src, int n4) {
    int idx = blockIdx.x * blockDim.x + threadIdx.x;
    if (idx >= n4) return;
    float4 v = ((const float4*)src)[idx];
    __half hx = __float2half(v.x), hy = __float2half(v.y);
    __half hz = __float2half(v.z), hw = __float2half(v.w);
    __half lx = __float2half(v.x - __half2float(hx));
    __half ly = __float2half(v.y - __half2float(hy));
    __half lz = __float2half(v.z - __half2float(hz));
    __half lw = __float2half(v.w - __half2float(hw));
    ((uint2*)g_iwh)[idx] = make_uint2(h2u(hx, hy), h2u(hz, hw));
    ((uint2*)g_iwl)[idx] = make_uint2(h2u(lx, ly), h2u(lz, lw));
}

// W [k][j] -> g_wf [j][k] single fp16
__global__ void wsplit_kernel(const float* __restrict__ W) {
    __shared__ float t[32][33];
    int bk = blockIdx.x * 32;
    int bj = blockIdx.y * 32;
    int tx = threadIdx.x, ty = threadIdx.y;
    for (int i = ty; i < 32; i += 8) t[i][tx] = W[(bk + i) * NH + bj + tx];
    __syncthreads();
    for (int i = ty; i < 32; i += 8)
        g_wf[(bj + i) * NH + bk + tx] = __float2half(t[tx][i]);
}

// ---------------------------------------------------------------------------
// Input projection: fp16 2-product HMMA. A = x (single fp16), B = in_w hi/lo.
// 128r x 64j tile, 512 threads (R14 structure).
// ---------------------------------------------------------------------------
__global__ void __launch_bounds__(512) proj_kernel(
    const float* __restrict__ bias, const float* __restrict__ eps,
    float* __restrict__ out)
{
    extern __shared__ char smem[];
    const uint32_t sb = smem_u32(smem);
    const int tid = threadIdx.x;
    const int l = tid & 31, w = tid >> 5;
    const int j0 = blockIdx.x * 64;
    const int r0 = blockIdx.y * 128;
    const int wm = (w & 7) * 16;
    const int wn = (w >> 3) * 32;

    const uint32_t aX = sb + PJ_X + (wm + (l & 15)) * ROWB + (l >> 4) * 16;
    const uint32_t brow = wn + ((l >> 4) << 3) + (l & 7);
    const uint32_t boff = ((l >> 3) & 1) * 16;
    const uint32_t b0Hi = sb + PJ_WHI + brow * ROWB + boff;
    const uint32_t b1Hi = b0Hi + 16 * ROWB;
    const uint32_t b0Lo = b0Hi + (PJ_WLO - PJ_WHI);
    const uint32_t b1Lo = b1Hi + (PJ_WLO - PJ_WHI);

    const int xr = tid >> 2, xc = tid & 3;   // x: 4 threads/row, 64B each
    const int wr = tid >> 3, wc = tid & 7;   // w: 8 threads/row, 32B each

    float acc[4][4];
#pragma unroll
    for (int n = 0; n < 4; n++)
#pragma unroll
        for (int i = 0; i < 4; i++) acc[n][i] = 0.0f;

#pragma unroll
    for (int kc = 0; kc < 2; kc++) {
        const int kb = kc * 128;
        if (kc) __syncthreads();
        {
            const char* sx = (const char*)(g_xf + (size_t)(r0 + xr) * NI + kb) + xc * 64;
            char* dx = smem + PJ_X + xr * ROWB + xc * 64;
#pragma unroll
            for (int i = 0; i < 4; i++)
                *(uint4*)(dx + i * 16) = *(const uint4*)(sx + i * 16);
            const char* swh = (const char*)(g_iwh + (size_t)(j0 + wr) * NI + kb) + wc * 32;
            const char* swl = (const char*)(g_iwl + (size_t)(j0 + wr) * NI + kb) + wc * 32;
            char* dwh = smem + PJ_WHI + wr * ROWB + wc * 32;
            char* dwl = smem + PJ_WLO + wr * ROWB + wc * 32;
            *(uint4*)dwh = *(const uint4*)swh;
            *(uint4*)(dwh + 16) = *(const uint4*)(swh + 16);
            *(uint4*)dwl = *(const uint4*)swl;
            *(uint4*)(dwl + 16) = *(const uint4*)(swl + 16);
        }
        __syncthreads();

#pragma unroll
        for (int kk = 0; kk < 8; kk++) {
            const uint32_t off = kk * 32;
            uint32_t ah[4], bh0[4], bh1[4], bl0[4], bl1[4];
            LDSM4(ah, aX + off);
            LDSM4(bh0, b0Hi + off);
            LDSM4(bh1, b1Hi + off);
            LDSM4(bl0, b0Lo + off);
            LDSM4(bl1, b1Lo + off);
            MMAF16816(acc[0], ah, bh0[0], bh0[1]);
            MMAF16816(acc[1], ah, bh0[2], bh0[3]);
            MMAF16816(acc[2], ah, bh1[0], bh1[1]);
            MMAF16816(acc[3], ah, bh1[2], bh1[3]);
            MMAF16816(acc[0], ah, bl0[0], bl0[1]);
            MMAF16816(acc[1], ah, bl0[2], bl0[3]);
            MMAF16816(acc[2], ah, bl1[0], bl1[1]);
            MMAF16816(acc[3], ah, bl1[2], bl1[3]);
        }
    }

    const int er = r0 + wm + (l >> 2);
    const int ejc = j0 + wn + 2 * (l & 3);
#pragma unroll
    for (int n = 0; n < 4; n++) {
        int j = ejc + 8 * n;
        float2 bi = *(const float2*)(bias + j);
        long off0 = (long)er * NH + j;
        float2 ev0 = *(const float2*)(eps + off0);
        *(float2*)(out + off0) = make_float2(acc[n][0] + bi.x + NOISEF * ev0.x,
                                             acc[n][1] + bi.y + NOISEF * ev0.y);
        long off1 = (long)(er + 8) * NH + j;
        float2 ev1 = *(const float2*)(eps + off1);
        *(float2*)(out + off1) = make_float2(acc[n][2] + bi.x + NOISEF * ev1.x,
                                             acc[n][3] + bi.y + NOISEF * ev1.y);
    }
}

// ---------------------------------------------------------------------------
// Persistent scan: 128 blocks x 512 threads. SINGLE-fp16 W, 1-product HMMA.
// Point-to-point release/acquire sync; single planar fp16 h staging.
// ---------------------------------------------------------------------------
__global__ void __launch_bounds__(512, 1) scan_kernel(float* __restrict__ out)
{
    extern __shared__ char smem[];
    const uint32_t sb = smem_u32(smem);
    const int tid = threadIdx.x;
    const int l = tid & 31, w = tid >> 5;
    const int nt = blockIdx.x & 15;
    const int ks = blockIdx.x >> 4;
    const int j0 = nt * 64;
    const int k0 = ks * 128;

    // Load W^T fp16 tile [64 j][128 k] into padded smem (once)
    {
        int r = tid >> 3, c = tid & 7;
        *(uint4*)(smem + SM_W + r * ROWB + c * 32) =
            *(const uint4*)((const char*)(g_wf + (size_t)(j0 + r) * NH + k0) + c * 32);
        *(uint4*)(smem + SM_W + r * ROWB + c * 32 + 16) =
            *(const uint4*)((const char*)(g_wf + (size_t)(j0 + r) * NH + k0) + c * 32 + 16);
    }

    // 16-warp partition: warp covers 16 j x 16 b
    const int wm = (w & 3) * 16;    // j offset
    const int wn = (w >> 2) * 16;   // b offset
    const uint32_t aW = sb + SM_W + (wm + (l & 15)) * ROWB + (l >> 4) * 16;
    const uint32_t brow = wn + ((l >> 4) << 3) + (l & 7);
    const uint32_t boff = ((l >> 3) & 1) * 16;
    const uint32_t b0 = sb + SM_B + brow * ROWB + boff;

    __syncthreads();

    // Hoist A fragments (W fp16) into registers
    uint32_t Ah[8][4];
#pragma unroll
    for (int kk = 0; kk < 8; kk++) LDSM4(Ah[kk], aW + kk * 32);

    // slab-store coords (pair layout [b/2][j][2])
    const int sj0 = j0 + wm + (l >> 2);
    const int sb0 = wn + 2 * (l & 3);

    // epilogue coords: one cell per thread: b in [8ks, 8ks+8), 64 j of tile nt
    const int ej = j0 + (tid & 63);
    const int eb = 8 * ks + (tid >> 6);
    const float alf = g_alpha[ej];

    // staging coords: 512 threads, each 16 fp16 of one b-row (32B)
    const int stb = tid >> 3, stc = tid & 7;
    char* dB = smem + SM_B + stb * ROWB + stc * 32;

    for (int t = 0; t < TT; t++) {
        // early prefetch of pre-activation (only this block touches it)
        const long o0 = ((long)eb * TT + t) * NH + ej;
        const float p0 = out[o0];

        // point-to-point waits (3 warps poll in parallel, acquire loads)
        if (t > 0) {
            const int tgt = 8 * t;
            if (tid == 0)  { while (ldacq(&g_ecnt[2 * ks]) < tgt) __nanosleep(16); }
            if (tid == 32) { while (ldacq(&g_ecnt[2 * ks + 1]) < tgt) __nanosleep(16); }
            if (tid == 64) { while (ldacq(&g_ecnt[nt]) < tgt) __nanosleep(16); }
            __syncthreads();
        }

        // stage h slice: single planar fp16, pure LDG.128 -> STS.128
        {
            const char* sh = (const char*)(g_hf[t & 1] + stb * NH + k0) + stc * 32;
            uint4 v0 = __ldcg((const uint4*)sh);
            uint4 v1 = __ldcg((const uint4*)(sh + 16));
            *(uint4*)dB = v0;
            *(uint4*)(dB + 16) = v1;
        }

        // prefetch step t-1 hidden state (covered by ecnt waits)
        const float h0 = __ldcg(&g_h32[t & 1][eb * NH + ej]);

        __syncthreads();

        // GEMM: 8 k-steps of 16, fp16 1-product, A in registers
        float acc[2][4];
#pragma unroll
        for (int n = 0; n < 2; n++)
#pragma unroll
            for (int i = 0; i < 4; i++) acc[n][i] = 0.0f;

#pragma unroll
        for (int kk = 0; kk < 8; kk++) {
            uint32_t bb[4];
            LDSM4(bb, b0 + kk * 32);
            MMAF16816(acc[0], Ah[kk], bb[0], bb[1]);
            MMAF16816(acc[1], Ah[kk], bb[2], bb[3]);
        }

        // store slab, pair layout
        {
            float* part = g_part[ks];
#pragma unroll
            for (int n = 0; n < 2; n++) {
                int pr = (sb0 + 8 * n) >> 1;
                *(float2*)(part + (size_t)pr * 2048 + sj0 * 2) =
                    make_float2(acc[n][0], acc[n][1]);
                *(float2*)(part + (size_t)pr * 2048 + (sj0 + 8) * 2) =
                    make_float2(acc[n][2], acc[n][3]);
            }
        }

        // release slab writes, rendezvous on tile nt's 8 slabs
        __syncthreads();
        if (tid == 0) {
            red_rel(&g_cnt[nt]);
            while (ldacq(&g_cnt[nt]) < 8 * (t + 1)) __nanosleep(16);
        }
        __syncthreads();

        // distributed epilogue: one cell per thread
        {
            const size_t poff = (size_t)(eb >> 1) * 2048 + ej * 2 + (eb & 1);
            float s0 = 0.0f;
#pragma unroll
            for (int q = 0; q < NKS; q++) s0 += __ldcg(&g_part[q][poff]);
            float n0 = (1.0f - alf) * h0 + alf * ftanh(p0 + s0);
            out[o0] = n0;
            g_h32[(t + 1) & 1][eb * NH + ej] = n0;
            g_hf[(t + 1) & 1][eb * NH + ej] = __float2half(n0);
        }

        // release epilogue writes for step t of tile nt
        __syncthreads();
        if (tid == 0) red_rel(&g_ecnt[nt]);
    }
}

extern "C" void kernel_launch(void* const* d_in, const int* in_sizes, int n_in,
                              void* d_out, int out_size) {
    const float* x    = (const float*)d_in[0];  // [B,T,I]
    const float* eps  = (const float*)d_in[1];  // [B,T,H]
    const float* in_w = (const float*)d_in[2];  // [H,I]
    const float* in_b = (const float*)d_in[3];  // [H]
    const float* W    = (const float*)d_in[4];  // [H,H]
    const float* taus = (const float*)d_in[5];  // [H]
    float* out = (float*)d_out;                 // [B,T,H]

    static int attr_done = 0;
    if (!attr_done) {
        cudaFuncSetAttribute(scan_kernel, cudaFuncAttributeMaxDynamicSharedMemorySize, SM_TOTAL);
        cudaFuncSetAttribute(proj_kernel, cudaFuncAttributeMaxDynamicSharedMemorySize, PJ_TOTAL);
        attr_done = 1;
    }

    init_kernel<<<(NB * NH + 255) / 256, 256>>>(taus);
    wsplit_kernel<<<dim3(NH / 32, NH / 32), dim3(32, 8)>>>(W);
    splitx_kernel<<<(NB * TT * NI / 4 + 255) / 256, 256>>>(x, NB * TT * NI / 4);
    splitw_kernel<<<(NH * NI / 4 + 255) / 256, 256>>>(in_w, NH * NI / 4);

    dim3 pgrid(NH / 64, (NB * TT) / 128);   // (16, 256)
    proj_kernel<<<pgrid, 512, PJ_TOTAL>>>(in_b, eps, out);

    scan_kernel<<<NBLK, 512, SM_TOTAL>>>(out);
}

// round 17
// speedup vs baseline: 3.4583x; 1.0233x over previous
#include <cuda_runtime.h>
#include <cuda_fp16.h>
#include <math.h>
#include <stdint.h>

#define NB 64
#define TT 512
#define NI 256
#define NH 1024
#define NOISEF 0.1f
#define NKS 8             // k-slices of 128
#define NTILE 16          // j-tiles of 64
#define NBLK 128

// ---- static device scratch ----
__device__ float g_h32[2][NB * NH];            // fp32 hidden state, double buf
__device__ __half g_hf[2][NB * NH];            // fp16 h (single, planar)
__device__ float g_part[NKS][NB * NH];         // split-K slabs, plain [b][j]
__device__ float g_alpha[NH];
__device__ __half g_wf[NH * NH];               // [j][k] = fp16(W[k][j]) single
__device__ __half g_xf[NB * TT * NI];          // fp16(x) [r][k]  (proj)
__device__ __half g_iwh[NH * NI];              // fp16(in_w) [j][k] (proj, single)
__device__ int g_cnt[NTILE];                   // slab arrivals per tile (monotonic)
__device__ int g_ecnt[NTILE];                  // epilogue parts per tile (monotonic)

// scan smem layout (272B-padded rows of 128 fp16)
#define SM_W   0
#define SM_B   17408
#define SM_TOTAL 34816
#define ROWB 272

// proj smem layout: x tile 128 rows (single), w tile 64 rows (single)
#define PJ_X   0
#define PJ_W   34816
#define PJ_TOTAL 52224

static __device__ __forceinline__ uint32_t smem_u32(const void* p) {
    uint32_t a;
    asm("{ .reg .u64 t; cvta.to.shared.u64 t, %1; cvt.u32.u64 %0, t; }" : "=r"(a) : "l"(p));
    return a;
}
static __device__ __forceinline__ int ldacq(const int* p) {
    int v;
    asm volatile("ld.acquire.gpu.global.b32 %0, [%1];" : "=r"(v) : "l"(p) : "memory");
    return v;
}
static __device__ __forceinline__ void red_rel(int* p) {
    asm volatile("red.release.gpu.global.add.s32 [%0], 1;" :: "l"(p) : "memory");
}

#define LDSM4(r, a)                                                             \
    asm volatile("ldmatrix.sync.aligned.m8n8.x4.shared.b16 {%0,%1,%2,%3}, [%4];" \
        : "=r"((r)[0]), "=r"((r)[1]), "=r"((r)[2]), "=r"((r)[3]) : "r"(a))

#define MMAF16816(d, a, b0, b1)                                                 \
    asm volatile("mma.sync.aligned.m16n8k16.row.col.f32.f16.f16.f32 "           \
        "{%0,%1,%2,%3}, {%4,%5,%6,%7}, {%8,%9}, {%0,%1,%2,%3};"                 \
        : "+f"((d)[0]), "+f"((d)[1]), "+f"((d)[2]), "+f"((d)[3])                \
        : "r"((a)[0]), "r"((a)[1]), "r"((a)[2]), "r"((a)[3]), "r"(b0), "r"(b1))

static __device__ __forceinline__ uint32_t h2u(__half a, __half b) {
    __half2 h = __halves2half2(a, b);
    return *reinterpret_cast<uint32_t*>(&h);
}
static __device__ __forceinline__ float ftanh(float x) {
    float e = __expf(2.0f * x);
    return 1.0f - __fdividef(2.0f, e + 1.0f);
}

__global__ void init_kernel(const float* __restrict__ taus) {
    int idx = blockIdx.x * blockDim.x + threadIdx.x;
    if (idx < NB * NH) {
        g_h32[0][idx] = 0.0f;
        g_hf[0][idx] = __float2half(0.0f);
    }
    if (idx < NH) {
        float s = 1.0f / (1.0f + expf(-taus[idx]));
        g_alpha[idx] = 10.0f / (s * 90.0f + 10.0f);
    }
    if (idx < NTILE) { g_cnt[idx] = 0; g_ecnt[idx] = 0; }
}

// f32 -> single fp16 (x or in_w)
__global__ void tohalf_kernel(const float* __restrict__ src, int which, int n4) {
    int idx = blockIdx.x * blockDim.x + threadIdx.x;
    if (idx >= n4) return;
    float4 v = ((const float4*)src)[idx];
    uint32_t u0 = h2u(__float2half(v.x), __float2half(v.y));
    uint32_t u1 = h2u(__float2half(v.z), __float2half(v.w));
    uint2* d = which ? (uint2*)g_iwh : (uint2*)g_xf;
    d[idx] = make_uint2(u0, u1);
}

// W [k][j] -> g_wf [j][k] single fp16
__global__ void wsplit_kernel(const float* __restrict__ W) {
    __shared__ float t[32][33];
    int bk = blockIdx.x * 32;
    int bj = blockIdx.y * 32;
    int tx = threadIdx.x, ty = threadIdx.y;
    for (int i = ty; i < 32; i += 8) t[i][tx] = W[(bk + i) * NH + bj + tx];
    __syncthreads();
    for (int i = ty; i < 32; i += 8)
        g_wf[(bj + i) * NH + bk + tx] = __float2half(t[tx][i]);
}

// ---------------------------------------------------------------------------
// Input projection: fp16 1-product HMMA. A = x, B = in_w, both single fp16.
// 128r x 64j tile, 512 threads.
// ---------------------------------------------------------------------------
__global__ void __launch_bounds__(512) proj_kernel(
    const float* __restrict__ bias, const float* __restrict__ eps,
    float* __restrict__ out)
{
    extern __shared__ char smem[];
    const uint32_t sb = smem_u32(smem);
    const int tid = threadIdx.x;
    const int l = tid & 31, w = tid >> 5;
    const int j0 = blockIdx.x * 64;
    const int r0 = blockIdx.y * 128;
    const int wm = (w & 7) * 16;
    const int wn = (w >> 3) * 32;

    const uint32_t aX = sb + PJ_X + (wm + (l & 15)) * ROWB + (l >> 4) * 16;
    const uint32_t brow = wn + ((l >> 4) << 3) + (l & 7);
    const uint32_t boff = ((l >> 3) & 1) * 16;
    const uint32_t b0W = sb + PJ_W + brow * ROWB + boff;
    const uint32_t b1W = b0W + 16 * ROWB;

    const int xr = tid >> 2, xc = tid & 3;   // x: 4 threads/row, 64B each
    const int wr = tid >> 3, wc = tid & 7;   // w: 8 threads/row, 32B each

    float acc[4][4];
#pragma unroll
    for (int n = 0; n < 4; n++)
#pragma unroll
        for (int i = 0; i < 4; i++) acc[n][i] = 0.0f;

#pragma unroll
    for (int kc = 0; kc < 2; kc++) {
        const int kb = kc * 128;
        if (kc) __syncthreads();
        {
            const char* sx = (const char*)(g_xf + (size_t)(r0 + xr) * NI + kb) + xc * 64;
            char* dx = smem + PJ_X + xr * ROWB + xc * 64;
#pragma unroll
            for (int i = 0; i < 4; i++)
                *(uint4*)(dx + i * 16) = *(const uint4*)(sx + i * 16);
            const char* sw = (const char*)(g_iwh + (size_t)(j0 + wr) * NI + kb) + wc * 32;
            char* dw = smem + PJ_W + wr * ROWB + wc * 32;
            *(uint4*)dw = *(const uint4*)sw;
            *(uint4*)(dw + 16) = *(const uint4*)(sw + 16);
        }
        __syncthreads();

#pragma unroll
        for (int kk = 0; kk < 8; kk++) {
            const uint32_t off = kk * 32;
            uint32_t ah[4], b0[4], b1[4];
            LDSM4(ah, aX + off);
            LDSM4(b0, b0W + off);
            LDSM4(b1, b1W + off);
            MMAF16816(acc[0], ah, b0[0], b0[1]);
            MMAF16816(acc[1], ah, b0[2], b0[3]);
            MMAF16816(acc[2], ah, b1[0], b1[1]);
            MMAF16816(acc[3], ah, b1[2], b1[3]);
        }
    }

    const int er = r0 + wm + (l >> 2);
    const int ejc = j0 + wn + 2 * (l & 3);
#pragma unroll
    for (int n = 0; n < 4; n++) {
        int j = ejc + 8 * n;
        float2 bi = *(const float2*)(bias + j);
        long off0 = (long)er * NH + j;
        float2 ev0 = *(const float2*)(eps + off0);
        *(float2*)(out + off0) = make_float2(acc[n][0] + bi.x + NOISEF * ev0.x,
                                             acc[n][1] + bi.y + NOISEF * ev0.y);
        long off1 = (long)(er + 8) * NH + j;
        float2 ev1 = *(const float2*)(eps + off1);
        *(float2*)(out + off1) = make_float2(acc[n][2] + bi.x + NOISEF * ev1.x,
                                             acc[n][3] + bi.y + NOISEF * ev1.y);
    }
}

// ---------------------------------------------------------------------------
// Persistent scan: 128 blocks x 512 threads. Single-fp16 W, 1-product HMMA.
// Point-to-point release/acquire sync; plain [b][j] slabs (coalesced epilogue).
// ---------------------------------------------------------------------------
__global__ void __launch_bounds__(512, 1) scan_kernel(float* __restrict__ out)
{
    extern __shared__ char smem[];
    const uint32_t sb = smem_u32(smem);
    const int tid = threadIdx.x;
    const int l = tid & 31, w = tid >> 5;
    const int nt = blockIdx.x & 15;
    const int ks = blockIdx.x >> 4;
    const int j0 = nt * 64;
    const int k0 = ks * 128;

    // Load W^T fp16 tile [64 j][128 k] into padded smem (once)
    {
        int r = tid >> 3, c = tid & 7;
        *(uint4*)(smem + SM_W + r * ROWB + c * 32) =
            *(const uint4*)((const char*)(g_wf + (size_t)(j0 + r) * NH + k0) + c * 32);
        *(uint4*)(smem + SM_W + r * ROWB + c * 32 + 16) =
            *(const uint4*)((const char*)(g_wf + (size_t)(j0 + r) * NH + k0) + c * 32 + 16);
    }

    // 16-warp partition: warp covers 16 j x 16 b
    const int wm = (w & 3) * 16;    // j offset
    const int wn = (w >> 2) * 16;   // b offset
    const uint32_t aW = sb + SM_W + (wm + (l & 15)) * ROWB + (l >> 4) * 16;
    const uint32_t brow = wn + ((l >> 4) << 3) + (l & 7);
    const uint32_t boff = ((l >> 3) & 1) * 16;
    const uint32_t b0 = sb + SM_B + brow * ROWB + boff;

    __syncthreads();

    // Hoist A fragments (W fp16) into registers
    uint32_t Ah[8][4];
#pragma unroll
    for (int kk = 0; kk < 8; kk++) LDSM4(Ah[kk], aW + kk * 32);

    // slab-store coords (plain [b][NH] layout)
    const int sj0 = j0 + wm + (l >> 2);
    const int sb0 = wn + 2 * (l & 3);

    // epilogue coords: one cell per thread: b in [8ks, 8ks+8), 64 j of tile nt
    const int ej = j0 + (tid & 63);
    const int eb = 8 * ks + (tid >> 6);
    const float alf = g_alpha[ej];

    // staging coords: 512 threads, each 16 fp16 of one b-row (32B)
    const int stb = tid >> 3, stc = tid & 7;
    char* dB = smem + SM_B + stb * ROWB + stc * 32;

    for (int t = 0; t < TT; t++) {
        // early prefetch of pre-activation (only this block touches it)
        const long o0 = ((long)eb * TT + t) * NH + ej;
        const float p0 = out[o0];

        // point-to-point waits (3 warps poll in parallel, acquire loads)
        if (t > 0) {
            const int tgt = 8 * t;
            if (tid == 0)  { while (ldacq(&g_ecnt[2 * ks]) < tgt) __nanosleep(8); }
            if (tid == 32) { while (ldacq(&g_ecnt[2 * ks + 1]) < tgt) __nanosleep(8); }
            if (tid == 64) { while (ldacq(&g_ecnt[nt]) < tgt) __nanosleep(8); }
            __syncthreads();
        }

        // stage h slice: single planar fp16, pure LDG.128 -> STS.128
        {
            const char* sh = (const char*)(g_hf[t & 1] + stb * NH + k0) + stc * 32;
            uint4 v0 = __ldcg((const uint4*)sh);
            uint4 v1 = __ldcg((const uint4*)(sh + 16));
            *(uint4*)dB = v0;
            *(uint4*)(dB + 16) = v1;
        }

        // prefetch step t-1 hidden state (covered by ecnt waits)
        const float h0 = __ldcg(&g_h32[t & 1][eb * NH + ej]);

        __syncthreads();

        // GEMM: 8 k-steps of 16, fp16 1-product, A in registers
        float acc[2][4];
#pragma unroll
        for (int n = 0; n < 2; n++)
#pragma unroll
            for (int i = 0; i < 4; i++) acc[n][i] = 0.0f;

#pragma unroll
        for (int kk = 0; kk < 8; kk++) {
            uint32_t bb[4];
            LDSM4(bb, b0 + kk * 32);
            MMAF16816(acc[0], Ah[kk], bb[0], bb[1]);
            MMAF16816(acc[1], Ah[kk], bb[2], bb[3]);
        }

        // store slab, plain [b][NH] layout (scalar stores; coalesced reads later)
        {
            float* part = g_part[ks];
#pragma unroll
            for (int n = 0; n < 2; n++) {
                int b = sb0 + 8 * n;
                part[(size_t)b * NH + sj0] = acc[n][0];
                part[(size_t)(b + 1) * NH + sj0] = acc[n][1];
                part[(size_t)b * NH + sj0 + 8] = acc[n][2];
                part[(size_t)(b + 1) * NH + sj0 + 8] = acc[n][3];
            }
        }

        // release slab writes, rendezvous on tile nt's 8 slabs
        __syncthreads();
        if (tid == 0) {
            red_rel(&g_cnt[nt]);
            while (ldacq(&g_cnt[nt]) < 8 * (t + 1)) __nanosleep(8);
        }
        __syncthreads();

        // distributed epilogue: one cell per thread, fully coalesced slab reads
        {
            const size_t poff = (size_t)eb * NH + ej;
            float s0 = 0.0f;
#pragma unroll
            for (int q = 0; q < NKS; q++) s0 += __ldcg(&g_part[q][poff]);
            float n0 = (1.0f - alf) * h0 + alf * ftanh(p0 + s0);
            out[o0] = n0;
            g_h32[(t + 1) & 1][eb * NH + ej] = n0;
            g_hf[(t + 1) & 1][eb * NH + ej] = __float2half(n0);
        }

        // release epilogue writes for step t of tile nt
        __syncthreads();
        if (tid == 0) red_rel(&g_ecnt[nt]);
    }
}

extern "C" void kernel_launch(void* const* d_in, const int* in_sizes, int n_in,
                              void* d_out, int out_size) {
    const float* x    = (const float*)d_in[0];  // [B,T,I]
    const float* eps  = (const float*)d_in[1];  // [B,T,H]
    const float* in_w = (const float*)d_in[2];  // [H,I]
    const float* in_b = (const float*)d_in[3];  // [H]
    const float* W    = (const float*)d_in[4];  // [H,H]
    const float* taus = (const float*)d_in[5];  // [H]
    float* out = (float*)d_out;                 // [B,T,H]

    static int attr_done = 0;
    if (!attr_done) {
        cudaFuncSetAttribute(scan_kernel, cudaFuncAttributeMaxDynamicSharedMemorySize, SM_TOTAL);
        cudaFuncSetAttribute(proj_kernel, cudaFuncAttributeMaxDynamicSharedMemorySize, PJ_TOTAL);
        attr_done = 1;
    }

    init_kernel<<<(NB * NH + 255) / 256, 256>>>(taus);
    wsplit_kernel<<<dim3(NH / 32, NH / 32), dim3(32, 8)>>>(W);
    tohalf_kernel<<<(NB * TT * NI / 4 + 255) / 256, 256>>>(x, 0, NB * TT * NI / 4);
    tohalf_kernel<<<(NH * NI / 4 + 255) / 256, 256>>>(in_w, 1, NH * NI / 4);

    dim3 pgrid(NH / 64, (NB * TT) / 128);   // (16, 256)
    proj_kernel<<<pgrid, 512, PJ_TOTAL>>>(in_b, eps, out);

    scan_kernel<<<NBLK, 512, SM_TOTAL>>>(out);
}